// round 8
// baseline (speedup 1.0000x reference)
#include <cuda_runtime.h>
#include <cstdint>

#define NN   50000
#define NP   50048            // padded rows = 391 * 128
#define EE   800000
#define INF  512
#define HF   128
#define OF   64
#define GBLK 391              // ceil(50000/128)

// ---------------- scratch (static device globals; zero-initialized) ---------
__device__ float g_WAT [(size_t)NN * HF];      // WA transposed: [N, H]
__device__ float g_cat [(size_t)NP * 2 * HF];  // [NP, 256] (xA | xX); tail rows stay 0
__device__ float g_h1  [(size_t)NP * HF];
__device__ float g_t   [(size_t)NP * HF];
__device__ float g_Wf2p[OF * HF];              // BN-folded
__device__ float g_bf2p[OF];
__device__ int   g_hist[NN];
__device__ int   g_off [NN + 1];
__device__ int   g_cur [NN];
__device__ int   g_dst [EE];
__device__ int   g_rmin;
__device__ float g_sum  [HF];
__device__ float g_sumsq[HF];

// ---------------- helpers ----------------------------------------------------
__device__ __forceinline__ float rna(float f) {
    float r; asm("cvt.rna.tf32.f32 %0, %1;" : "=f"(r) : "f"(f)); return r;
}
__device__ __forceinline__ uint32_t rnau(float f) { return __float_as_uint(rna(f)); }
__device__ __forceinline__ uint32_t s2u(const void* p) {
    uint32_t a;
    asm("{ .reg .u64 t; cvta.to.shared.u64 t, %1; cvt.u32.u64 %0, t; }" : "=r"(a) : "l"(p));
    return a;
}
__device__ __forceinline__ void cp8(uint32_t d, const void* s) {
    asm volatile("cp.async.ca.shared.global [%0], [%1], 8;" :: "r"(d), "l"(s));
}
__device__ __forceinline__ void cp8z(uint32_t d, const void* s, int sz) {
    asm volatile("cp.async.ca.shared.global [%0], [%1], 8, %2;" :: "r"(d), "l"(s), "r"(sz));
}

// ---------------- init -------------------------------------------------------
__global__ void k_init() {
    int i = blockIdx.x * blockDim.x + threadIdx.x;
    if (i < NN) g_hist[i] = 0;
    if (blockIdx.x == 0) {
        if (threadIdx.x < HF) { g_sum[threadIdx.x] = 0.f; g_sumsq[threadIdx.x] = 0.f; }
        if (threadIdx.x == 0) g_rmin = 0x7fffffff;
    }
}

// ---------------- histogram + row min (4 edges / thread) ---------------------
__global__ void k_hist(const int* __restrict__ row, int E) {
    int base = (blockIdx.x * blockDim.x + threadIdx.x) * 4;
    int rmn = 0x7fffffff;
    #pragma unroll
    for (int u = 0; u < 4; ++u) {
        int e = base + u;
        if (e < E) {
            int r = row[e];
            rmn = min(rmn, r);
            atomicAdd(&g_hist[r], 1);
        }
    }
    unsigned wm = __reduce_min_sync(0xffffffffu, (unsigned)rmn);
    if ((threadIdx.x & 31) == 0) atomicMin(&g_rmin, (int)wm);
}

// ---------------- single-block exclusive scan --------------------------------
__global__ void k_scan(int E) {
    __shared__ int ssum[1024];
    int tid = threadIdx.x;
    const int chunk = (NN + 1023) / 1024;
    int beg = tid * chunk;
    int end = min(beg + chunk, NN);
    int s = 0;
    for (int i = beg; i < end; ++i) s += g_hist[i];
    ssum[tid] = s;
    __syncthreads();
    for (int ofs = 1; ofs < 1024; ofs <<= 1) {
        int v = (tid >= ofs) ? ssum[tid - ofs] : 0;
        __syncthreads();
        ssum[tid] += v;
        __syncthreads();
    }
    int run = (tid == 0) ? 0 : ssum[tid - 1];
    for (int i = beg; i < end; ++i) {
        g_off[i] = run; g_cur[i] = run; run += g_hist[i];
    }
    if (tid == 1023) g_off[NN] = run;
}

// ---------------- bin edges by row (4 edges / thread, independent chains) ----
__global__ void k_bin(const int* __restrict__ row, const int* __restrict__ col, int E) {
    int base = (blockIdx.x * blockDim.x + threadIdx.x) * 4;
    int r[4], c[4], p[4];
    bool ok[4];
    #pragma unroll
    for (int u = 0; u < 4; ++u) {
        int e = base + u;
        ok[u] = e < E;
        if (ok[u]) { r[u] = row[e]; c[u] = col[e]; }
    }
    #pragma unroll
    for (int u = 0; u < 4; ++u)
        if (ok[u]) p[u] = atomicAdd(&g_cur[r[u]], 1);
    #pragma unroll
    for (int u = 0; u < 4; ++u)
        if (ok[u]) g_dst[p[u]] = c[u];
}

// ---------------- transpose WA [H,N] -> WAT [N,H] ----------------------------
__global__ void k_transpose(const float* __restrict__ WA) {
    __shared__ float tile[32][33];
    int n0 = blockIdx.x * 32, h0 = blockIdx.y * 32;
    int tx = threadIdx.x, ty = threadIdx.y;
    #pragma unroll
    for (int j = 0; j < 32; j += 8) {
        int h = h0 + ty + j, n = n0 + tx;
        tile[ty + j][tx] = (n < NN) ? WA[(size_t)h * NN + n] : 0.f;
    }
    __syncthreads();
    #pragma unroll
    for (int j = 0; j < 32; j += 8) {
        int n = n0 + ty + j, h = h0 + tx;
        if (n < NN) g_WAT[(size_t)n * HF + h] = tile[tx][ty + j];
    }
}

// ---------------- gather xA = segsum(WAT[col]) + bA -> cat[:, :128] ----------
__global__ void k_gather(const float* __restrict__ bA) {
    int w    = (blockIdx.x * blockDim.x + threadIdx.x) >> 5;
    int lane = threadIdx.x & 31;
    if (w >= NN) return;
    int bkt = w + g_rmin;
    int s = 0, e = 0;
    if (bkt < NN) { s = g_off[bkt]; e = g_off[bkt + 1]; }
    float4 acc = *(const float4*)(bA + lane * 4);
    int j = s;
    for (; j + 4 <= e; j += 4) {
        int c0 = g_dst[j], c1 = g_dst[j + 1], c2 = g_dst[j + 2], c3 = g_dst[j + 3];
        float4 v0 = *(const float4*)(g_WAT + (size_t)c0 * HF + lane * 4);
        float4 v1 = *(const float4*)(g_WAT + (size_t)c1 * HF + lane * 4);
        float4 v2 = *(const float4*)(g_WAT + (size_t)c2 * HF + lane * 4);
        float4 v3 = *(const float4*)(g_WAT + (size_t)c3 * HF + lane * 4);
        float4 p, q;
        p.x = v0.x + v1.x; p.y = v0.y + v1.y; p.z = v0.z + v1.z; p.w = v0.w + v1.w;
        q.x = v2.x + v3.x; q.y = v2.y + v3.y; q.z = v2.z + v3.z; q.w = v2.w + v3.w;
        acc.x += p.x + q.x; acc.y += p.y + q.y; acc.z += p.z + q.z; acc.w += p.w + q.w;
    }
    for (; j < e; ++j) {
        int c = g_dst[j];
        float4 v = *(const float4*)(g_WAT + (size_t)c * HF + lane * 4);
        acc.x += v.x; acc.y += v.y; acc.z += v.z; acc.w += v.w;
    }
    *((float4*)(g_cat + (size_t)w * (2 * HF) + lane * 4)) = acc;
}

// ---------------- tf32 mma.sync GEMM (4-stage cp.async pipeline) -------------
// C = A[M,K] @ B[N,K]^T + bias. Operands tf32-rounded (rna) at fragment load.
// EPI 0: plain, 1: +skip(cat lo+hi)+relu, 2: relu. GUARD: zfill A rows >= NN.
// STATS: fused BN column sums/sumsq of stored values.
template<int BN, int EPI, int GUARD, int STATS>
__global__ __launch_bounds__(256, 2)
void k_mm(const float* __restrict__ A, int lda,
          const float* __restrict__ B,
          const float* __restrict__ bias,
          float* __restrict__ C, int ldc, int K,
          const float* __restrict__ skip)
{
    constexpr int BM = 128, BK = 16, STR = 20, S = 4;
    constexpr int WXn = 4, WTN = BN / WXn;        // warp tile N: 32 or 16
    constexpr int NF = WTN / 8;                   // 4 or 2
    constexpr int MF = 4;                         // 64/16
    __shared__ float As[S][BM * STR];
    __shared__ float Bs[S][BN * STR];
    __shared__ float s_sum[BN], s_sq[BN];

    const int tid  = threadIdx.x;
    const int lane = tid & 31, warp = tid >> 5;
    const int wy = warp / WXn, wx = warp % WXn;
    const int g = lane >> 2, tg = lane & 3;
    const int bm = blockIdx.x * BM;

    if (STATS && tid < BN) { s_sum[tid] = 0.f; s_sq[tid] = 0.f; }

    float acc[MF][NF][4];
    #pragma unroll
    for (int i = 0; i < MF; ++i)
        #pragma unroll
        for (int j = 0; j < NF; ++j)
            #pragma unroll
            for (int c = 0; c < 4; ++c) acc[i][j][c] = 0.f;

    const uint32_t aS = s2u(As), bS = s2u(Bs);
    const int T = K / BK;

    auto load_tiles = [&](int t, int st) {
        const int k0 = t * BK;
        #pragma unroll
        for (int i = 0; i < BM * 8 / 256; ++i) {       // A: 4 chunks/thread
            int idx = tid + i * 256;
            int r = idx >> 3, ch = idx & 7;
            uint32_t d = aS + (uint32_t)(st * BM * STR + r * STR + ch * 2) * 4;
            if (GUARD) {
                bool v = (bm + r) < NN;
                cp8z(d, A + (v ? ((size_t)(bm + r) * lda + k0 + ch * 2) : 0), v ? 8 : 0);
            } else {
                cp8(d, A + (size_t)(bm + r) * lda + k0 + ch * 2);
            }
        }
        #pragma unroll
        for (int i = 0; i < BN * 8 / 256; ++i) {       // B
            int idx = tid + i * 256;
            int r = idx >> 3, ch = idx & 7;
            cp8(bS + (uint32_t)(st * BN * STR + r * STR + ch * 2) * 4,
                B + (size_t)r * K + k0 + ch * 2);
        }
        asm volatile("cp.async.commit_group;");
    };

    // prologue: stages 0..2 in flight
    #pragma unroll
    for (int s = 0; s < S - 1; ++s)
        if (s < T) load_tiles(s, s);

    for (int t = 0; t < T; ++t) {
        asm volatile("cp.async.wait_group %0;" :: "n"(S - 2));  // tile t resident
        __syncthreads();                                        // stage (t-1)&3 free
        if (t + S - 1 < T) load_tiles(t + S - 1, (t + S - 1) & (S - 1));

        const float* as = As[t & (S - 1)];
        const float* bs = Bs[t & (S - 1)];
        #pragma unroll
        for (int ks = 0; ks < 2; ++ks) {
            uint32_t af[MF][4], bf[NF][2];
            #pragma unroll
            for (int mf = 0; mf < MF; ++mf) {
                int r0 = (wy * 64 + mf * 16 + g) * STR + ks * 8 + tg;
                af[mf][0] = rnau(as[r0]);
                af[mf][1] = rnau(as[r0 + 8 * STR]);
                af[mf][2] = rnau(as[r0 + 4]);
                af[mf][3] = rnau(as[r0 + 8 * STR + 4]);
            }
            #pragma unroll
            for (int nf = 0; nf < NF; ++nf) {
                int rb = (wx * WTN + nf * 8 + g) * STR + ks * 8 + tg;
                bf[nf][0] = rnau(bs[rb]);
                bf[nf][1] = rnau(bs[rb + 4]);
            }
            #pragma unroll
            for (int mf = 0; mf < MF; ++mf)
                #pragma unroll
                for (int nf = 0; nf < NF; ++nf)
                    asm volatile(
                        "mma.sync.aligned.m16n8k8.row.col.f32.tf32.tf32.f32 "
                        "{%0,%1,%2,%3},{%4,%5,%6,%7},{%8,%9},{%0,%1,%2,%3};"
                        : "+f"(acc[mf][nf][0]), "+f"(acc[mf][nf][1]),
                          "+f"(acc[mf][nf][2]), "+f"(acc[mf][nf][3])
                        : "r"(af[mf][0]), "r"(af[mf][1]), "r"(af[mf][2]), "r"(af[mf][3]),
                          "r"(bf[nf][0]), "r"(bf[nf][1]));
        }
    }

    // ---- epilogue (+ optional fused BN stats) -------------------------------
    #pragma unroll
    for (int nf = 0; nf < NF; ++nf) {
        int n0 = wx * WTN + nf * 8 + tg * 2;
        float b0 = bias[n0], b1 = bias[n0 + 1];
        float ps0 = 0.f, pq0 = 0.f, ps1 = 0.f, pq1 = 0.f;
        #pragma unroll
        for (int mf = 0; mf < MF; ++mf) {
            #pragma unroll
            for (int half = 0; half < 2; ++half) {
                int m = bm + wy * 64 + mf * 16 + g + half * 8;
                if (m >= NN) continue;
                float v0 = acc[mf][nf][half * 2 + 0] + b0;
                float v1 = acc[mf][nf][half * 2 + 1] + b1;
                if (EPI == 1) {
                    const float* sp = skip + (size_t)m * 256;
                    v0 += sp[n0]     + sp[128 + n0];
                    v1 += sp[n0 + 1] + sp[128 + n0 + 1];
                    v0 = fmaxf(v0, 0.f); v1 = fmaxf(v1, 0.f);
                } else if (EPI == 2) {
                    v0 = fmaxf(v0, 0.f); v1 = fmaxf(v1, 0.f);
                }
                *(float2*)(C + (size_t)m * ldc + n0) = make_float2(v0, v1);
                if (STATS) { ps0 += v0; pq0 += v0 * v0; ps1 += v1; pq1 += v1 * v1; }
            }
        }
        if (STATS) {
            #pragma unroll
            for (int msk = 16; msk >= 4; msk >>= 1) {
                ps0 += __shfl_xor_sync(0xffffffffu, ps0, msk);
                pq0 += __shfl_xor_sync(0xffffffffu, pq0, msk);
                ps1 += __shfl_xor_sync(0xffffffffu, ps1, msk);
                pq1 += __shfl_xor_sync(0xffffffffu, pq1, msk);
            }
            if (g == 0) {
                atomicAdd(&s_sum[n0],     ps0); atomicAdd(&s_sq[n0],     pq0);
                atomicAdd(&s_sum[n0 + 1], ps1); atomicAdd(&s_sq[n0 + 1], pq1);
            }
        }
    }
    if (STATS) {
        __syncthreads();
        if (tid < BN) {
            atomicAdd(&g_sum[tid],   s_sum[tid]);
            atomicAdd(&g_sumsq[tid], s_sq[tid]);
        }
    }
}

// ---------------- fold BN affine into Wf2/bf2 --------------------------------
__global__ void k_fold(const float* __restrict__ gamma, const float* __restrict__ beta,
                       const float* __restrict__ Wf2,   const float* __restrict__ bf2,
                       int M) {
    __shared__ float a[HF], b[HF];
    int t = threadIdx.x;
    if (t < HF) {
        float inv  = 1.f / (float)M;
        float mean = g_sum[t] * inv;
        float var  = g_sumsq[t] * inv - mean * mean;
        float av   = gamma[t] * rsqrtf(var + 1e-5f);
        a[t] = av;
        b[t] = beta[t] - mean * av;
    }
    __syncthreads();
    for (int i = t; i < OF * HF; i += blockDim.x)
        g_Wf2p[i] = Wf2[i] * a[i & (HF - 1)];
    if (t < OF) {
        float s = bf2[t];
        for (int h = 0; h < HF; ++h) s += b[h] * Wf2[t * HF + h];
        g_bf2p[t] = s;
    }
}

// -----------------------------------------------------------------------------
extern "C" void kernel_launch(void* const* d_in, const int* in_sizes, int n_in,
                              void* d_out, int out_size) {
    const float* x     = (const float*)d_in[0];
    const int*   ei    = (const int*)  d_in[1];
    const float* WA    = (const float*)d_in[2];
    const float* bA    = (const float*)d_in[3];
    const float* WX    = (const float*)d_in[4];
    const float* bX    = (const float*)d_in[5];
    const float* W     = (const float*)d_in[6];
    const float* bW    = (const float*)d_in[7];
    const float* Wf1   = (const float*)d_in[8];
    const float* bf1   = (const float*)d_in[9];
    const float* gamma = (const float*)d_in[10];
    const float* beta  = (const float*)d_in[11];
    const float* Wf2   = (const float*)d_in[12];
    const float* bf2   = (const float*)d_in[13];
    float* out = (float*)d_out;

    const int E = in_sizes[1] / 2;
    const int M = NN;
    const int* row = ei;
    const int* col = ei + E;

    float *pCat, *pH1, *pT, *pW2, *pB2;
    cudaGetSymbolAddress((void**)&pCat, g_cat);
    cudaGetSymbolAddress((void**)&pH1,  g_h1);
    cudaGetSymbolAddress((void**)&pT,   g_t);
    cudaGetSymbolAddress((void**)&pW2,  g_Wf2p);
    cudaGetSymbolAddress((void**)&pB2,  g_bf2p);

    // ---- edge pipeline -------------------------------------------------------
    k_init<<<(NN + 255) / 256, 256>>>();
    k_hist<<<(E / 4 + 255) / 256, 256>>>(row, E);
    k_scan<<<1, 1024>>>(E);
    k_bin<<<(E / 4 + 255) / 256, 256>>>(row, col, E);
    k_transpose<<<dim3((NN + 31) / 32, HF / 32), dim3(32, 8)>>>(WA);
    k_gather<<<(NN * 32 + 255) / 256, 256>>>(bA);          // xA -> cat[:, :128]

    // ---- xX = x @ WX^T + bX  -> cat[:, 128:]  (raw x, guarded tail) ---------
    k_mm<128, 0, 1, 0><<<GBLK, 256>>>(x, INF, WX, bX, pCat + HF, 2 * HF, INF, nullptr);

    // ---- h1 = relu(cat @ W^T + bW + xA + xX) --------------------------------
    k_mm<128, 1, 0, 0><<<GBLK, 256>>>(pCat, 2 * HF, W, bW, pH1, HF, 2 * HF, pCat);

    // ---- t = relu(h1 @ Wf1^T + bf1)  + fused BN stats -----------------------
    k_mm<128, 2, 0, 1><<<GBLK, 256>>>(pH1, HF, Wf1, bf1, pT, HF, HF, nullptr);

    // ---- fold BN into Wf2/bf2 ------------------------------------------------
    k_fold<<<1, 256>>>(gamma, beta, Wf2, bf2, M);

    // ---- out = bn(t) @ Wf2'^T + bf2' ----------------------------------------
    k_mm<64, 0, 0, 0><<<GBLK, 256>>>(pT, HF, pW2, pB2, out, OF, HF, nullptr);
}

// round 10
// speedup vs baseline: 1.0237x; 1.0237x over previous
#include <cuda_runtime.h>
#include <cstdint>

#define NN   50000
#define NP   50048            // padded rows = 391 * 128
#define EE   800000
#define INF  512
#define HF   128
#define OF   64
#define GBLK 391              // ceil(50000/128)

// ---------------- scratch (static device globals; zero-initialized) ---------
__device__ float g_WAT [(size_t)NN * HF];      // WA transposed: [N, H]
__device__ float g_cat [(size_t)NP * 2 * HF];  // [NP, 256] (xA | xX); tail rows stay 0
__device__ float g_t   [(size_t)NP * HF];
__device__ float g_Wf2p[OF * HF];              // BN-folded
__device__ float g_bf2p[OF];
__device__ int   g_hist[NN];
__device__ int   g_off [NN + 1];
__device__ int   g_cur [NN];
__device__ int   g_dst [EE];
__device__ int   g_rmin;
__device__ float g_sum  [HF];
__device__ float g_sumsq[HF];

// ---------------- helpers ----------------------------------------------------
__device__ __forceinline__ float rna(float f) {
    float r; asm("cvt.rna.tf32.f32 %0, %1;" : "=f"(r) : "f"(f)); return r;
}
__device__ __forceinline__ uint32_t rnau(float f) { return __float_as_uint(rna(f)); }
__device__ __forceinline__ uint32_t s2u(const void* p) {
    uint32_t a;
    asm("{ .reg .u64 t; cvta.to.shared.u64 t, %1; cvt.u32.u64 %0, t; }" : "=r"(a) : "l"(p));
    return a;
}
__device__ __forceinline__ void cp8(uint32_t d, const void* s) {
    asm volatile("cp.async.ca.shared.global [%0], [%1], 8;" :: "r"(d), "l"(s));
}
__device__ __forceinline__ void cp8z(uint32_t d, const void* s, int sz) {
    asm volatile("cp.async.ca.shared.global [%0], [%1], 8, %2;" :: "r"(d), "l"(s), "r"(sz));
}
#define MMA_TF32(acc, af, bf)                                                 \
    asm volatile(                                                             \
        "mma.sync.aligned.m16n8k8.row.col.f32.tf32.tf32.f32 "                 \
        "{%0,%1,%2,%3},{%4,%5,%6,%7},{%8,%9},{%0,%1,%2,%3};"                  \
        : "+f"((acc)[0]), "+f"((acc)[1]), "+f"((acc)[2]), "+f"((acc)[3])      \
        : "r"((af)[0]), "r"((af)[1]), "r"((af)[2]), "r"((af)[3]),             \
          "r"((bf)[0]), "r"((bf)[1]))

// ---------------- init -------------------------------------------------------
__global__ void k_init() {
    int i = blockIdx.x * blockDim.x + threadIdx.x;
    if (i < NN) g_hist[i] = 0;
    if (blockIdx.x == 0) {
        if (threadIdx.x < HF) { g_sum[threadIdx.x] = 0.f; g_sumsq[threadIdx.x] = 0.f; }
        if (threadIdx.x == 0) g_rmin = 0x7fffffff;
    }
}

// ---------------- histogram + row min (4 edges / thread) ---------------------
__global__ void k_hist(const int* __restrict__ row, int E) {
    int base = (blockIdx.x * blockDim.x + threadIdx.x) * 4;
    int rmn = 0x7fffffff;
    #pragma unroll
    for (int u = 0; u < 4; ++u) {
        int e = base + u;
        if (e < E) {
            int r = row[e];
            rmn = min(rmn, r);
            atomicAdd(&g_hist[r], 1);
        }
    }
    unsigned wm = __reduce_min_sync(0xffffffffu, (unsigned)rmn);
    if ((threadIdx.x & 31) == 0) atomicMin(&g_rmin, (int)wm);
}

// ---------------- single-block exclusive scan --------------------------------
__global__ void k_scan(int E) {
    __shared__ int ssum[1024];
    int tid = threadIdx.x;
    const int chunk = (NN + 1023) / 1024;
    int beg = tid * chunk;
    int end = min(beg + chunk, NN);
    int s = 0;
    for (int i = beg; i < end; ++i) s += g_hist[i];
    ssum[tid] = s;
    __syncthreads();
    for (int ofs = 1; ofs < 1024; ofs <<= 1) {
        int v = (tid >= ofs) ? ssum[tid - ofs] : 0;
        __syncthreads();
        ssum[tid] += v;
        __syncthreads();
    }
    int run = (tid == 0) ? 0 : ssum[tid - 1];
    for (int i = beg; i < end; ++i) {
        g_off[i] = run; g_cur[i] = run; run += g_hist[i];
    }
    if (tid == 1023) g_off[NN] = run;
}

// ---------------- bin edges by row (4 edges / thread) ------------------------
__global__ void k_bin(const int* __restrict__ row, const int* __restrict__ col, int E) {
    int base = (blockIdx.x * blockDim.x + threadIdx.x) * 4;
    int r[4], c[4], p[4];
    bool ok[4];
    #pragma unroll
    for (int u = 0; u < 4; ++u) {
        int e = base + u;
        ok[u] = e < E;
        if (ok[u]) { r[u] = row[e]; c[u] = col[e]; }
    }
    #pragma unroll
    for (int u = 0; u < 4; ++u)
        if (ok[u]) p[u] = atomicAdd(&g_cur[r[u]], 1);
    #pragma unroll
    for (int u = 0; u < 4; ++u)
        if (ok[u]) g_dst[p[u]] = c[u];
}

// ---------------- transpose WA [H,N] -> WAT [N,H] ----------------------------
__global__ void k_transpose(const float* __restrict__ WA) {
    __shared__ float tile[32][33];
    int n0 = blockIdx.x * 32, h0 = blockIdx.y * 32;
    int tx = threadIdx.x, ty = threadIdx.y;
    #pragma unroll
    for (int j = 0; j < 32; j += 8) {
        int h = h0 + ty + j, n = n0 + tx;
        tile[ty + j][tx] = (n < NN) ? WA[(size_t)h * NN + n] : 0.f;
    }
    __syncthreads();
    #pragma unroll
    for (int j = 0; j < 32; j += 8) {
        int n = n0 + ty + j, h = h0 + tx;
        if (n < NN) g_WAT[(size_t)n * HF + h] = tile[tx][ty + j];
    }
}

// ---------------- gather xA = segsum(WAT[col]) + bA -> cat[:, :128] ----------
__global__ void k_gather(const float* __restrict__ bA) {
    int w    = (blockIdx.x * blockDim.x + threadIdx.x) >> 5;
    int lane = threadIdx.x & 31;
    if (w >= NN) return;
    int bkt = w + g_rmin;
    int s = 0, e = 0;
    if (bkt < NN) { s = g_off[bkt]; e = g_off[bkt + 1]; }
    float4 acc = *(const float4*)(bA + lane * 4);
    int j = s;
    for (; j + 4 <= e; j += 4) {
        int c0 = g_dst[j], c1 = g_dst[j + 1], c2 = g_dst[j + 2], c3 = g_dst[j + 3];
        float4 v0 = *(const float4*)(g_WAT + (size_t)c0 * HF + lane * 4);
        float4 v1 = *(const float4*)(g_WAT + (size_t)c1 * HF + lane * 4);
        float4 v2 = *(const float4*)(g_WAT + (size_t)c2 * HF + lane * 4);
        float4 v3 = *(const float4*)(g_WAT + (size_t)c3 * HF + lane * 4);
        float4 p, q;
        p.x = v0.x + v1.x; p.y = v0.y + v1.y; p.z = v0.z + v1.z; p.w = v0.w + v1.w;
        q.x = v2.x + v3.x; q.y = v2.y + v3.y; q.z = v2.z + v3.z; q.w = v2.w + v3.w;
        acc.x += p.x + q.x; acc.y += p.y + q.y; acc.z += p.z + q.z; acc.w += p.w + q.w;
    }
    for (; j < e; ++j) {
        int c = g_dst[j];
        float4 v = *(const float4*)(g_WAT + (size_t)c * HF + lane * 4);
        acc.x += v.x; acc.y += v.y; acc.z += v.z; acc.w += v.w;
    }
    *((float4*)(g_cat + (size_t)w * (2 * HF) + lane * 4)) = acc;
}

// ---------------- tf32 mma.sync GEMM (2-stage, proven) -----------------------
// C = A[M,K] @ B[N,K]^T + bias. EPI 0: plain, 2: relu. GUARD: zfill rows>=NN.
template<int BN, int EPI, int GUARD>
__global__ __launch_bounds__(256)
void k_mm(const float* __restrict__ A, int lda,
          const float* __restrict__ B,
          const float* __restrict__ bias,
          float* __restrict__ C, int ldc, int K)
{
    constexpr int BM = 128, BK = 16, STR = 20;
    constexpr int WXn = 4, WTN = BN / WXn;
    constexpr int NF = WTN / 8;
    constexpr int MF = 4;
    __shared__ float As[2][BM * STR];
    __shared__ float Bs[2][BN * STR];

    const int tid  = threadIdx.x;
    const int lane = tid & 31, warp = tid >> 5;
    const int wy = warp / WXn, wx = warp % WXn;
    const int g = lane >> 2, tg = lane & 3;
    const int bm = blockIdx.x * BM;

    float acc[MF][NF][4];
    #pragma unroll
    for (int i = 0; i < MF; ++i)
        #pragma unroll
        for (int j = 0; j < NF; ++j)
            #pragma unroll
            for (int c = 0; c < 4; ++c) acc[i][j][c] = 0.f;

    const uint32_t aS = s2u(As), bS = s2u(Bs);
    const int T = K / BK;

    auto load_tiles = [&](int t, int st) {
        const int k0 = t * BK;
        #pragma unroll
        for (int i = 0; i < BM * 8 / 256; ++i) {
            int idx = tid + i * 256;
            int r = idx >> 3, ch = idx & 7;
            uint32_t d = aS + (uint32_t)(st * BM * STR + r * STR + ch * 2) * 4;
            if (GUARD) {
                bool v = (bm + r) < NN;
                cp8z(d, A + (v ? ((size_t)(bm + r) * lda + k0 + ch * 2) : 0), v ? 8 : 0);
            } else {
                cp8(d, A + (size_t)(bm + r) * lda + k0 + ch * 2);
            }
        }
        #pragma unroll
        for (int i = 0; i < BN * 8 / 256; ++i) {
            int idx = tid + i * 256;
            int r = idx >> 3, ch = idx & 7;
            cp8(bS + (uint32_t)(st * BN * STR + r * STR + ch * 2) * 4,
                B + (size_t)r * K + k0 + ch * 2);
        }
        asm volatile("cp.async.commit_group;");
    };

    load_tiles(0, 0);

    for (int t = 0; t < T; ++t) {
        const int cur = t & 1;
        if (t + 1 < T) {
            load_tiles(t + 1, cur ^ 1);
            asm volatile("cp.async.wait_group 1;");
        } else {
            asm volatile("cp.async.wait_group 0;");
        }
        __syncthreads();

        const float* as = As[cur];
        const float* bs = Bs[cur];
        #pragma unroll
        for (int ks = 0; ks < 2; ++ks) {
            uint32_t af[MF][4], bf[NF][2];
            #pragma unroll
            for (int mf = 0; mf < MF; ++mf) {
                int r0 = (wy * 64 + mf * 16 + g) * STR + ks * 8 + tg;
                af[mf][0] = rnau(as[r0]);
                af[mf][1] = rnau(as[r0 + 8 * STR]);
                af[mf][2] = rnau(as[r0 + 4]);
                af[mf][3] = rnau(as[r0 + 8 * STR + 4]);
            }
            #pragma unroll
            for (int nf = 0; nf < NF; ++nf) {
                int rb = (wx * WTN + nf * 8 + g) * STR + ks * 8 + tg;
                bf[nf][0] = rnau(bs[rb]);
                bf[nf][1] = rnau(bs[rb + 4]);
            }
            #pragma unroll
            for (int mf = 0; mf < MF; ++mf)
                #pragma unroll
                for (int nf = 0; nf < NF; ++nf)
                    MMA_TF32(acc[mf][nf], af[mf], bf[nf]);
        }
        __syncthreads();
    }

    #pragma unroll
    for (int nf = 0; nf < NF; ++nf) {
        int n0 = wx * WTN + nf * 8 + tg * 2;
        float b0 = bias[n0], b1 = bias[n0 + 1];
        #pragma unroll
        for (int mf = 0; mf < MF; ++mf) {
            #pragma unroll
            for (int half = 0; half < 2; ++half) {
                int m = bm + wy * 64 + mf * 16 + g + half * 8;
                if (m >= NN) continue;
                float v0 = acc[mf][nf][half * 2 + 0] + b0;
                float v1 = acc[mf][nf][half * 2 + 1] + b1;
                if (EPI == 2) { v0 = fmaxf(v0, 0.f); v1 = fmaxf(v1, 0.f); }
                *(float2*)(C + (size_t)m * ldc + n0) = make_float2(v0, v1);
            }
        }
    }
}

// ---------------- fused GEMM2+GEMM3 (dynamic smem) ---------------------------
// Stage B: h1 = relu(cat @ W^T + bW + xA + xX)  -> smem (rna-rounded)
// Stage C: t  = relu(h1 @ Wf1^T + bf1)          -> g_t, + fused BN stats
// dyn smem layout (floats): As[2][128*20] | Bs[2][128*20] | h1s[128*132]
#define MM23_AS     0
#define MM23_BS     (2 * 128 * 20)
#define MM23_H1     (4 * 128 * 20)
#define MM23_FLOATS (MM23_H1 + 128 * 132)
#define MM23_BYTES  (MM23_FLOATS * 4)

__global__ __launch_bounds__(256)
void k_mm23(const float* __restrict__ W,   const float* __restrict__ bW,
            const float* __restrict__ Wf1, const float* __restrict__ bf1)
{
    constexpr int BM = 128, BK = 16, STR = 20, STR2 = 132;
    constexpr int WXn = 4, WTN = 32, NF = 4, MF = 4;
    extern __shared__ float dyn[];
    float* As  = dyn + MM23_AS;     // [2][BM*STR]
    float* Bs  = dyn + MM23_BS;     // [2][HF*STR]
    float* h1s = dyn + MM23_H1;     // [BM*STR2]
    __shared__ float s_sum[HF], s_sq[HF];

    const int tid  = threadIdx.x;
    const int lane = tid & 31, warp = tid >> 5;
    const int wy = warp / WXn, wx = warp % WXn;
    const int g = lane >> 2, tg = lane & 3;
    const int bm = blockIdx.x * BM;
    const float* cat = g_cat;

    if (tid < HF) { s_sum[tid] = 0.f; s_sq[tid] = 0.f; }

    float acc[MF][NF][4];
    #pragma unroll
    for (int i = 0; i < MF; ++i)
        #pragma unroll
        for (int j = 0; j < NF; ++j)
            #pragma unroll
            for (int c = 0; c < 4; ++c) acc[i][j][c] = 0.f;

    const uint32_t aS = s2u(As), bS = s2u(Bs);

    // ---------------- stage B: K = 256 over cat/W ---------------------------
    auto loadB = [&](int t, int st) {
        const int k0 = t * BK;
        #pragma unroll
        for (int i = 0; i < 4; ++i) {
            int idx = tid + i * 256;
            int r = idx >> 3, ch = idx & 7;
            cp8(aS + (uint32_t)(st * BM * STR + r * STR + ch * 2) * 4,
                cat + (size_t)(bm + r) * 256 + k0 + ch * 2);
        }
        #pragma unroll
        for (int i = 0; i < 4; ++i) {
            int idx = tid + i * 256;
            int r = idx >> 3, ch = idx & 7;
            cp8(bS + (uint32_t)(st * HF * STR + r * STR + ch * 2) * 4,
                W + (size_t)r * 256 + k0 + ch * 2);
        }
        asm volatile("cp.async.commit_group;");
    };

    loadB(0, 0);
    for (int t = 0; t < 16; ++t) {
        const int cur = t & 1;
        if (t + 1 < 16) {
            loadB(t + 1, cur ^ 1);
            asm volatile("cp.async.wait_group 1;");
        } else {
            asm volatile("cp.async.wait_group 0;");
        }
        __syncthreads();
        const float* as = As + cur * BM * STR;
        const float* bs = Bs + cur * HF * STR;
        #pragma unroll
        for (int ks = 0; ks < 2; ++ks) {
            uint32_t af[MF][4], bf[NF][2];
            #pragma unroll
            for (int mf = 0; mf < MF; ++mf) {
                int r0 = (wy * 64 + mf * 16 + g) * STR + ks * 8 + tg;
                af[mf][0] = rnau(as[r0]);
                af[mf][1] = rnau(as[r0 + 8 * STR]);
                af[mf][2] = rnau(as[r0 + 4]);
                af[mf][3] = rnau(as[r0 + 8 * STR + 4]);
            }
            #pragma unroll
            for (int nf = 0; nf < NF; ++nf) {
                int rb = (wx * WTN + nf * 8 + g) * STR + ks * 8 + tg;
                bf[nf][0] = rnau(bs[rb]);
                bf[nf][1] = rnau(bs[rb + 4]);
            }
            #pragma unroll
            for (int mf = 0; mf < MF; ++mf)
                #pragma unroll
                for (int nf = 0; nf < NF; ++nf)
                    MMA_TF32(acc[mf][nf], af[mf], bf[nf]);
        }
        __syncthreads();
    }

    // prefetch stage-C B tile 0 (Wf1) while accumulators drain to smem
    {
        #pragma unroll
        for (int i = 0; i < 4; ++i) {
            int idx = tid + i * 256;
            int r = idx >> 3, ch = idx & 7;
            cp8(bS + (uint32_t)(r * STR + ch * 2) * 4,
                Wf1 + (size_t)r * HF + ch * 2);
        }
        asm volatile("cp.async.commit_group;");
    }

    // stage-B epilogue: skip + relu + rna -> h1s
    #pragma unroll
    for (int nf = 0; nf < NF; ++nf) {
        int n0 = wx * WTN + nf * 8 + tg * 2;
        float b0 = bW[n0], b1 = bW[n0 + 1];
        #pragma unroll
        for (int mf = 0; mf < MF; ++mf) {
            #pragma unroll
            for (int half = 0; half < 2; ++half) {
                int ml = wy * 64 + mf * 16 + g + half * 8;
                const float* sp = cat + (size_t)(bm + ml) * 256;
                float v0 = acc[mf][nf][half * 2 + 0] + b0 + sp[n0]     + sp[128 + n0];
                float v1 = acc[mf][nf][half * 2 + 1] + b1 + sp[n0 + 1] + sp[128 + n0 + 1];
                v0 = rna(fmaxf(v0, 0.f)); v1 = rna(fmaxf(v1, 0.f));
                *(float2*)(h1s + ml * STR2 + n0) = make_float2(v0, v1);
                acc[mf][nf][half * 2 + 0] = 0.f;
                acc[mf][nf][half * 2 + 1] = 0.f;
            }
        }
    }
    __syncthreads();

    // ---------------- stage C: K = 128, A from h1s, B = Wf1 -----------------
    auto loadC = [&](int t, int st) {
        const int k0 = t * BK;
        #pragma unroll
        for (int i = 0; i < 4; ++i) {
            int idx = tid + i * 256;
            int r = idx >> 3, ch = idx & 7;
            cp8(bS + (uint32_t)(st * HF * STR + r * STR + ch * 2) * 4,
                Wf1 + (size_t)r * HF + k0 + ch * 2);
        }
        asm volatile("cp.async.commit_group;");
    };

    for (int t = 0; t < 8; ++t) {
        const int cur = t & 1;
        if (t + 1 < 8) {
            loadC(t + 1, cur ^ 1);
            asm volatile("cp.async.wait_group 1;");
        } else {
            asm volatile("cp.async.wait_group 0;");
        }
        __syncthreads();
        const float* bs = Bs + cur * HF * STR;
        const int kb = t * BK;
        #pragma unroll
        for (int ks = 0; ks < 2; ++ks) {
            uint32_t af[MF][4], bf[NF][2];
            #pragma unroll
            for (int mf = 0; mf < MF; ++mf) {
                int r0 = (wy * 64 + mf * 16 + g) * STR2 + kb + ks * 8 + tg;
                af[mf][0] = __float_as_uint(h1s[r0]);
                af[mf][1] = __float_as_uint(h1s[r0 + 8 * STR2]);
                af[mf][2] = __float_as_uint(h1s[r0 + 4]);
                af[mf][3] = __float_as_uint(h1s[r0 + 8 * STR2 + 4]);
            }
            #pragma unroll
            for (int nf = 0; nf < NF; ++nf) {
                int rb = (wx * WTN + nf * 8 + g) * STR + ks * 8 + tg;
                bf[nf][0] = rnau(bs[rb]);
                bf[nf][1] = rnau(bs[rb + 4]);
            }
            #pragma unroll
            for (int mf = 0; mf < MF; ++mf)
                #pragma unroll
                for (int nf = 0; nf < NF; ++nf)
                    MMA_TF32(acc[mf][nf], af[mf], bf[nf]);
        }
        __syncthreads();
    }

    // stage-C epilogue: relu + store g_t + fused BN stats
    #pragma unroll
    for (int nf = 0; nf < NF; ++nf) {
        int n0 = wx * WTN + nf * 8 + tg * 2;
        float b0 = bf1[n0], b1 = bf1[n0 + 1];
        float ps0 = 0.f, pq0 = 0.f, ps1 = 0.f, pq1 = 0.f;
        #pragma unroll
        for (int mf = 0; mf < MF; ++mf) {
            #pragma unroll
            for (int half = 0; half < 2; ++half) {
                int m = bm + wy * 64 + mf * 16 + g + half * 8;
                if (m >= NN) continue;
                float v0 = fmaxf(acc[mf][nf][half * 2 + 0] + b0, 0.f);
                float v1 = fmaxf(acc[mf][nf][half * 2 + 1] + b1, 0.f);
                *(float2*)(g_t + (size_t)m * HF + n0) = make_float2(v0, v1);
                ps0 += v0; pq0 += v0 * v0; ps1 += v1; pq1 += v1 * v1;
            }
        }
        #pragma unroll
        for (int msk = 16; msk >= 4; msk >>= 1) {
            ps0 += __shfl_xor_sync(0xffffffffu, ps0, msk);
            pq0 += __shfl_xor_sync(0xffffffffu, pq0, msk);
            ps1 += __shfl_xor_sync(0xffffffffu, ps1, msk);
            pq1 += __shfl_xor_sync(0xffffffffu, pq1, msk);
        }
        if (g == 0) {
            atomicAdd(&s_sum[n0],     ps0); atomicAdd(&s_sq[n0],     pq0);
            atomicAdd(&s_sum[n0 + 1], ps1); atomicAdd(&s_sq[n0 + 1], pq1);
        }
    }
    __syncthreads();
    if (tid < HF) {
        atomicAdd(&g_sum[tid],   s_sum[tid]);
        atomicAdd(&g_sumsq[tid], s_sq[tid]);
    }
}

// ---------------- fold BN affine into Wf2/bf2 --------------------------------
__global__ void k_fold(const float* __restrict__ gamma, const float* __restrict__ beta,
                       const float* __restrict__ Wf2,   const float* __restrict__ bf2,
                       int M) {
    __shared__ float a[HF], b[HF];
    int t = threadIdx.x;
    if (t < HF) {
        float inv  = 1.f / (float)M;
        float mean = g_sum[t] * inv;
        float var  = g_sumsq[t] * inv - mean * mean;
        float av   = gamma[t] * rsqrtf(var + 1e-5f);
        a[t] = av;
        b[t] = beta[t] - mean * av;
    }
    __syncthreads();
    for (int i = t; i < OF * HF; i += blockDim.x)
        g_Wf2p[i] = Wf2[i] * a[i & (HF - 1)];
    if (t < OF) {
        float s = bf2[t];
        for (int h = 0; h < HF; ++h) s += b[h] * Wf2[t * HF + h];
        g_bf2p[t] = s;
    }
}

// -----------------------------------------------------------------------------
extern "C" void kernel_launch(void* const* d_in, const int* in_sizes, int n_in,
                              void* d_out, int out_size) {
    const float* x     = (const float*)d_in[0];
    const int*   ei    = (const int*)  d_in[1];
    const float* WA    = (const float*)d_in[2];
    const float* bA    = (const float*)d_in[3];
    const float* WX    = (const float*)d_in[4];
    const float* bX    = (const float*)d_in[5];
    const float* W     = (const float*)d_in[6];
    const float* bW    = (const float*)d_in[7];
    const float* Wf1   = (const float*)d_in[8];
    const float* bf1   = (const float*)d_in[9];
    const float* gamma = (const float*)d_in[10];
    const float* beta  = (const float*)d_in[11];
    const float* Wf2   = (const float*)d_in[12];
    const float* bf2   = (const float*)d_in[13];
    float* out = (float*)d_out;

    const int E = in_sizes[1] / 2;
    const int M = NN;
    const int* row = ei;
    const int* col = ei + E;

    float *pCat, *pT, *pW2, *pB2;
    cudaGetSymbolAddress((void**)&pCat, g_cat);
    cudaGetSymbolAddress((void**)&pT,   g_t);
    cudaGetSymbolAddress((void**)&pW2,  g_Wf2p);
    cudaGetSymbolAddress((void**)&pB2,  g_bf2p);

    static int smem_set = 0;
    if (!smem_set) {
        cudaFuncSetAttribute(k_mm23, cudaFuncAttributeMaxDynamicSharedMemorySize,
                             MM23_BYTES);
        smem_set = 1;
    }

    // ---- edge pipeline -------------------------------------------------------
    k_init<<<(NN + 255) / 256, 256>>>();
    k_hist<<<(E / 4 + 255) / 256, 256>>>(row, E);
    k_scan<<<1, 1024>>>(E);
    k_bin<<<(E / 4 + 255) / 256, 256>>>(row, col, E);
    k_transpose<<<dim3((NN + 31) / 32, HF / 32), dim3(32, 8)>>>(WA);
    k_gather<<<(NN * 32 + 255) / 256, 256>>>(bA);          // xA -> cat[:, :128]

    // ---- xX = x @ WX^T + bX  -> cat[:, 128:] --------------------------------
    k_mm<128, 0, 1><<<GBLK, 256>>>(x, INF, WX, bX, pCat + HF, 2 * HF, INF);

    // ---- fused: h1 = relu(cat@W^T+bW+skip); t = relu(h1@Wf1^T+bf1) + stats --
    k_mm23<<<GBLK, 256, MM23_BYTES>>>(W, bW, Wf1, bf1);

    // ---- fold BN into Wf2/bf2 ------------------------------------------------
    k_fold<<<1, 256>>>(gamma, beta, Wf2, bf2, M);

    // ---- out = bn(t) @ Wf2'^T + bf2' ----------------------------------------
    k_mm<64, 0, 0><<<GBLK, 256>>>(pT, HF, pW2, pB2, out, OF, HF);
}

// round 11
// speedup vs baseline: 1.1641x; 1.1371x over previous
#include <cuda_runtime.h>
#include <cstdint>

#define NN   50000
#define NP   50048            // padded rows = 391 * 128
#define EE   800000
#define INF  512
#define HF   128
#define OF   64
#define GBLK 391              // ceil(50000/128)

// ---------------- scratch (static device globals; zero-initialized) ---------
__device__ float g_WAT [(size_t)NN * HF];      // WA transposed: [N, H]
__device__ float g_cat [(size_t)NP * 2 * HF];  // [NP, 256] (xA | xX); tail rows stay 0
__device__ float g_t   [(size_t)NP * HF];
__device__ float g_Wf2p[OF * HF];              // BN-folded
__device__ float g_bf2p[OF];
__device__ int   g_hist[NN];
__device__ int   g_off [NN + 1];
__device__ int   g_cur [NN];
__device__ int   g_dst [EE];
__device__ int   g_rmin;
__device__ float g_sum  [HF];
__device__ float g_sumsq[HF];

// ---------------- helpers ----------------------------------------------------
__device__ __forceinline__ float rna(float f) {
    float r; asm("cvt.rna.tf32.f32 %0, %1;" : "=f"(r) : "f"(f)); return r;
}
__device__ __forceinline__ uint32_t rnau(float f) { return __float_as_uint(rna(f)); }
__device__ __forceinline__ uint32_t s2u(const void* p) {
    uint32_t a;
    asm("{ .reg .u64 t; cvta.to.shared.u64 t, %1; cvt.u32.u64 %0, t; }" : "=r"(a) : "l"(p));
    return a;
}
__device__ __forceinline__ void cp16(uint32_t d, const void* s) {
    asm volatile("cp.async.cg.shared.global [%0], [%1], 16;" :: "r"(d), "l"(s));
}
__device__ __forceinline__ void cp16z(uint32_t d, const void* s, int sz) {
    asm volatile("cp.async.cg.shared.global [%0], [%1], 16, %2;" :: "r"(d), "l"(s), "r"(sz));
}
#define MMA_TF32(acc, af, bf)                                                 \
    asm volatile(                                                             \
        "mma.sync.aligned.m16n8k8.row.col.f32.tf32.tf32.f32 "                 \
        "{%0,%1,%2,%3},{%4,%5,%6,%7},{%8,%9},{%0,%1,%2,%3};"                  \
        : "+f"((acc)[0]), "+f"((acc)[1]), "+f"((acc)[2]), "+f"((acc)[3])      \
        : "r"((af)[0]), "r"((af)[1]), "r"((af)[2]), "r"((af)[3]),             \
          "r"((bf)[0]), "r"((bf)[1]))

// ---------------- init -------------------------------------------------------
__global__ void k_init() {
    int i = blockIdx.x * blockDim.x + threadIdx.x;
    if (i < NN) g_hist[i] = 0;
    if (blockIdx.x == 0) {
        if (threadIdx.x < HF) { g_sum[threadIdx.x] = 0.f; g_sumsq[threadIdx.x] = 0.f; }
        if (threadIdx.x == 0) g_rmin = 0x7fffffff;
    }
}

// ---------------- histogram + row min (4 edges / thread) ---------------------
__global__ void k_hist(const int* __restrict__ row, int E) {
    int base = (blockIdx.x * blockDim.x + threadIdx.x) * 4;
    int rmn = 0x7fffffff;
    #pragma unroll
    for (int u = 0; u < 4; ++u) {
        int e = base + u;
        if (e < E) {
            int r = row[e];
            rmn = min(rmn, r);
            atomicAdd(&g_hist[r], 1);
        }
    }
    unsigned wm = __reduce_min_sync(0xffffffffu, (unsigned)rmn);
    if ((threadIdx.x & 31) == 0) atomicMin(&g_rmin, (int)wm);
}

// ---------------- single-block exclusive scan --------------------------------
__global__ void k_scan(int E) {
    __shared__ int ssum[1024];
    int tid = threadIdx.x;
    const int chunk = (NN + 1023) / 1024;
    int beg = tid * chunk;
    int end = min(beg + chunk, NN);
    int s = 0;
    for (int i = beg; i < end; ++i) s += g_hist[i];
    ssum[tid] = s;
    __syncthreads();
    for (int ofs = 1; ofs < 1024; ofs <<= 1) {
        int v = (tid >= ofs) ? ssum[tid - ofs] : 0;
        __syncthreads();
        ssum[tid] += v;
        __syncthreads();
    }
    int run = (tid == 0) ? 0 : ssum[tid - 1];
    for (int i = beg; i < end; ++i) {
        g_off[i] = run; g_cur[i] = run; run += g_hist[i];
    }
    if (tid == 1023) g_off[NN] = run;
}

// ---------------- bin edges by row (4 edges / thread) ------------------------
__global__ void k_bin(const int* __restrict__ row, const int* __restrict__ col, int E) {
    int base = (blockIdx.x * blockDim.x + threadIdx.x) * 4;
    int r[4], c[4], p[4];
    bool ok[4];
    #pragma unroll
    for (int u = 0; u < 4; ++u) {
        int e = base + u;
        ok[u] = e < E;
        if (ok[u]) { r[u] = row[e]; c[u] = col[e]; }
    }
    #pragma unroll
    for (int u = 0; u < 4; ++u)
        if (ok[u]) p[u] = atomicAdd(&g_cur[r[u]], 1);
    #pragma unroll
    for (int u = 0; u < 4; ++u)
        if (ok[u]) g_dst[p[u]] = c[u];
}

// ---------------- transpose WA [H,N] -> WAT [N,H] ----------------------------
__global__ void k_transpose(const float* __restrict__ WA) {
    __shared__ float tile[32][33];
    int n0 = blockIdx.x * 32, h0 = blockIdx.y * 32;
    int tx = threadIdx.x, ty = threadIdx.y;
    #pragma unroll
    for (int j = 0; j < 32; j += 8) {
        int h = h0 + ty + j, n = n0 + tx;
        tile[ty + j][tx] = (n < NN) ? WA[(size_t)h * NN + n] : 0.f;
    }
    __syncthreads();
    #pragma unroll
    for (int j = 0; j < 32; j += 8) {
        int n = n0 + ty + j, h = h0 + tx;
        if (n < NN) g_WAT[(size_t)n * HF + h] = tile[tx][ty + j];
    }
}

// ---------------- gather xA = segsum(WAT[col]) + bA -> cat[:, :128] ----------
__global__ void k_gather(const float* __restrict__ bA) {
    int w    = (blockIdx.x * blockDim.x + threadIdx.x) >> 5;
    int lane = threadIdx.x & 31;
    if (w >= NN) return;
    int bkt = w + g_rmin;
    int s = 0, e = 0;
    if (bkt < NN) { s = g_off[bkt]; e = g_off[bkt + 1]; }
    float4 acc = *(const float4*)(bA + lane * 4);
    int j = s;
    for (; j + 4 <= e; j += 4) {
        int c0 = g_dst[j], c1 = g_dst[j + 1], c2 = g_dst[j + 2], c3 = g_dst[j + 3];
        float4 v0 = *(const float4*)(g_WAT + (size_t)c0 * HF + lane * 4);
        float4 v1 = *(const float4*)(g_WAT + (size_t)c1 * HF + lane * 4);
        float4 v2 = *(const float4*)(g_WAT + (size_t)c2 * HF + lane * 4);
        float4 v3 = *(const float4*)(g_WAT + (size_t)c3 * HF + lane * 4);
        float4 p, q;
        p.x = v0.x + v1.x; p.y = v0.y + v1.y; p.z = v0.z + v1.z; p.w = v0.w + v1.w;
        q.x = v2.x + v3.x; q.y = v2.y + v3.y; q.z = v2.z + v3.z; q.w = v2.w + v3.w;
        acc.x += p.x + q.x; acc.y += p.y + q.y; acc.z += p.z + q.z; acc.w += p.w + q.w;
    }
    for (; j < e; ++j) {
        int c = g_dst[j];
        float4 v = *(const float4*)(g_WAT + (size_t)c * HF + lane * 4);
        acc.x += v.x; acc.y += v.y; acc.z += v.z; acc.w += v.w;
    }
    *((float4*)(g_cat + (size_t)w * (2 * HF) + lane * 4)) = acc;
}

// ---------------- tf32 mma.sync GEMM (2-stage) -------------------------------
// C = A[M,K] @ B[N,K]^T + bias. EPI 0: plain, 2: relu. GUARD: zfill rows>=NN.
template<int BN, int EPI, int GUARD>
__global__ __launch_bounds__(256)
void k_mm(const float* __restrict__ A, int lda,
          const float* __restrict__ B,
          const float* __restrict__ bias,
          float* __restrict__ C, int ldc, int K)
{
    constexpr int BM = 128, BK = 16, STR = 20;
    constexpr int WXn = 4, WTN = BN / WXn;
    constexpr int NF = WTN / 8;
    constexpr int MF = 4;
    __shared__ __align__(16) float As[2][BM * STR];
    __shared__ __align__(16) float Bs[2][BN * STR];

    const int tid  = threadIdx.x;
    const int lane = tid & 31, warp = tid >> 5;
    const int wy = warp / WXn, wx = warp % WXn;
    const int g = lane >> 2, tg = lane & 3;
    const int bm = blockIdx.x * BM;

    float acc[MF][NF][4];
    #pragma unroll
    for (int i = 0; i < MF; ++i)
        #pragma unroll
        for (int j = 0; j < NF; ++j)
            #pragma unroll
            for (int c = 0; c < 4; ++c) acc[i][j][c] = 0.f;

    const uint32_t aS = s2u(As), bS = s2u(Bs);
    const int T = K / BK;

    auto load_tiles = [&](int t, int st) {
        const int k0 = t * BK;
        #pragma unroll
        for (int i = 0; i < BM * 4 / 256; ++i) {       // A: 16B chunks
            int idx = tid + i * 256;
            int r = idx >> 2, ch = idx & 3;
            uint32_t d = aS + (uint32_t)(st * BM * STR + r * STR + ch * 4) * 4;
            if (GUARD) {
                bool v = (bm + r) < NN;
                cp16z(d, A + (v ? ((size_t)(bm + r) * lda + k0 + ch * 4) : 0), v ? 16 : 0);
            } else {
                cp16(d, A + (size_t)(bm + r) * lda + k0 + ch * 4);
            }
        }
        #pragma unroll
        for (int i = 0; i < BN * 4 / 256; ++i) {       // B
            int idx = tid + i * 256;
            int r = idx >> 2, ch = idx & 3;
            cp16(bS + (uint32_t)(st * BN * STR + r * STR + ch * 4) * 4,
                 B + (size_t)r * K + k0 + ch * 4);
        }
        asm volatile("cp.async.commit_group;");
    };

    load_tiles(0, 0);

    for (int t = 0; t < T; ++t) {
        const int cur = t & 1;
        if (t + 1 < T) {
            load_tiles(t + 1, cur ^ 1);
            asm volatile("cp.async.wait_group 1;");
        } else {
            asm volatile("cp.async.wait_group 0;");
        }
        __syncthreads();

        const float* as = As[cur];
        const float* bs = Bs[cur];
        #pragma unroll
        for (int ks = 0; ks < 2; ++ks) {
            uint32_t af[MF][4], bf[NF][2];
            #pragma unroll
            for (int mf = 0; mf < MF; ++mf) {
                int r0 = (wy * 64 + mf * 16 + g) * STR + ks * 8 + tg;
                af[mf][0] = rnau(as[r0]);
                af[mf][1] = rnau(as[r0 + 8 * STR]);
                af[mf][2] = rnau(as[r0 + 4]);
                af[mf][3] = rnau(as[r0 + 8 * STR + 4]);
            }
            #pragma unroll
            for (int nf = 0; nf < NF; ++nf) {
                int rb = (wx * WTN + nf * 8 + g) * STR + ks * 8 + tg;
                bf[nf][0] = rnau(bs[rb]);
                bf[nf][1] = rnau(bs[rb + 4]);
            }
            #pragma unroll
            for (int mf = 0; mf < MF; ++mf)
                #pragma unroll
                for (int nf = 0; nf < NF; ++nf)
                    MMA_TF32(acc[mf][nf], af[mf], bf[nf]);
        }
        __syncthreads();
    }

    #pragma unroll
    for (int nf = 0; nf < NF; ++nf) {
        int n0 = wx * WTN + nf * 8 + tg * 2;
        float b0 = bias[n0], b1 = bias[n0 + 1];
        #pragma unroll
        for (int mf = 0; mf < MF; ++mf) {
            #pragma unroll
            for (int half = 0; half < 2; ++half) {
                int m = bm + wy * 64 + mf * 16 + g + half * 8;
                if (m >= NN) continue;
                float v0 = acc[mf][nf][half * 2 + 0] + b0;
                float v1 = acc[mf][nf][half * 2 + 1] + b1;
                if (EPI == 2) { v0 = fmaxf(v0, 0.f); v1 = fmaxf(v1, 0.f); }
                *(float2*)(C + (size_t)m * ldc + n0) = make_float2(v0, v1);
            }
        }
    }
}

// ---------------- fused GEMM2+GEMM3 (dynamic smem) ---------------------------
#define MM23_AS     0
#define MM23_BS     (2 * 128 * 20)
#define MM23_H1     (4 * 128 * 20)
#define MM23_FLOATS (MM23_H1 + 128 * 132)
#define MM23_BYTES  (MM23_FLOATS * 4)

__global__ __launch_bounds__(256)
void k_mm23(const float* __restrict__ W,   const float* __restrict__ bW,
            const float* __restrict__ Wf1, const float* __restrict__ bf1)
{
    constexpr int BM = 128, BK = 16, STR = 20, STR2 = 132;
    constexpr int WXn = 4, WTN = 32, NF = 4, MF = 4;
    extern __shared__ float dyn[];
    float* As  = dyn + MM23_AS;
    float* Bs  = dyn + MM23_BS;
    float* h1s = dyn + MM23_H1;
    __shared__ float s_sum[HF], s_sq[HF];

    const int tid  = threadIdx.x;
    const int lane = tid & 31, warp = tid >> 5;
    const int wy = warp / WXn, wx = warp % WXn;
    const int g = lane >> 2, tg = lane & 3;
    const int bm = blockIdx.x * BM;
    const float* cat = g_cat;

    if (tid < HF) { s_sum[tid] = 0.f; s_sq[tid] = 0.f; }

    float acc[MF][NF][4];
    #pragma unroll
    for (int i = 0; i < MF; ++i)
        #pragma unroll
        for (int j = 0; j < NF; ++j)
            #pragma unroll
            for (int c = 0; c < 4; ++c) acc[i][j][c] = 0.f;

    const uint32_t aS = s2u(As), bS = s2u(Bs);

    auto loadB = [&](int t, int st) {
        const int k0 = t * BK;
        #pragma unroll
        for (int i = 0; i < 2; ++i) {
            int idx = tid + i * 256;
            int r = idx >> 2, ch = idx & 3;
            cp16(aS + (uint32_t)(st * BM * STR + r * STR + ch * 4) * 4,
                 cat + (size_t)(bm + r) * 256 + k0 + ch * 4);
        }
        #pragma unroll
        for (int i = 0; i < 2; ++i) {
            int idx = tid + i * 256;
            int r = idx >> 2, ch = idx & 3;
            cp16(bS + (uint32_t)(st * HF * STR + r * STR + ch * 4) * 4,
                 W + (size_t)r * 256 + k0 + ch * 4);
        }
        asm volatile("cp.async.commit_group;");
    };

    loadB(0, 0);
    for (int t = 0; t < 16; ++t) {
        const int cur = t & 1;
        if (t + 1 < 16) {
            loadB(t + 1, cur ^ 1);
            asm volatile("cp.async.wait_group 1;");
        } else {
            asm volatile("cp.async.wait_group 0;");
        }
        __syncthreads();
        const float* as = As + cur * BM * STR;
        const float* bs = Bs + cur * HF * STR;
        #pragma unroll
        for (int ks = 0; ks < 2; ++ks) {
            uint32_t af[MF][4], bf[NF][2];
            #pragma unroll
            for (int mf = 0; mf < MF; ++mf) {
                int r0 = (wy * 64 + mf * 16 + g) * STR + ks * 8 + tg;
                af[mf][0] = rnau(as[r0]);
                af[mf][1] = rnau(as[r0 + 8 * STR]);
                af[mf][2] = rnau(as[r0 + 4]);
                af[mf][3] = rnau(as[r0 + 8 * STR + 4]);
            }
            #pragma unroll
            for (int nf = 0; nf < NF; ++nf) {
                int rb = (wx * WTN + nf * 8 + g) * STR + ks * 8 + tg;
                bf[nf][0] = rnau(bs[rb]);
                bf[nf][1] = rnau(bs[rb + 4]);
            }
            #pragma unroll
            for (int mf = 0; mf < MF; ++mf)
                #pragma unroll
                for (int nf = 0; nf < NF; ++nf)
                    MMA_TF32(acc[mf][nf], af[mf], bf[nf]);
        }
        __syncthreads();
    }

    // prefetch stage-C B tile 0 (Wf1)
    {
        #pragma unroll
        for (int i = 0; i < 2; ++i) {
            int idx = tid + i * 256;
            int r = idx >> 2, ch = idx & 3;
            cp16(bS + (uint32_t)(r * STR + ch * 4) * 4,
                 Wf1 + (size_t)r * HF + ch * 4);
        }
        asm volatile("cp.async.commit_group;");
    }

    // stage-B epilogue: skip + relu + rna -> h1s
    #pragma unroll
    for (int nf = 0; nf < NF; ++nf) {
        int n0 = wx * WTN + nf * 8 + tg * 2;
        float b0 = bW[n0], b1 = bW[n0 + 1];
        #pragma unroll
        for (int mf = 0; mf < MF; ++mf) {
            #pragma unroll
            for (int half = 0; half < 2; ++half) {
                int ml = wy * 64 + mf * 16 + g + half * 8;
                const float* sp = cat + (size_t)(bm + ml) * 256;
                float v0 = acc[mf][nf][half * 2 + 0] + b0 + sp[n0]     + sp[128 + n0];
                float v1 = acc[mf][nf][half * 2 + 1] + b1 + sp[n0 + 1] + sp[128 + n0 + 1];
                v0 = rna(fmaxf(v0, 0.f)); v1 = rna(fmaxf(v1, 0.f));
                *(float2*)(h1s + ml * STR2 + n0) = make_float2(v0, v1);
                acc[mf][nf][half * 2 + 0] = 0.f;
                acc[mf][nf][half * 2 + 1] = 0.f;
            }
        }
    }
    __syncthreads();

    // stage C: K = 128, A from h1s, B = Wf1
    auto loadC = [&](int t, int st) {
        const int k0 = t * BK;
        #pragma unroll
        for (int i = 0; i < 2; ++i) {
            int idx = tid + i * 256;
            int r = idx >> 2, ch = idx & 3;
            cp16(bS + (uint32_t)(st * HF * STR + r * STR + ch * 4) * 4,
                 Wf1 + (size_t)r * HF + k0 + ch * 4);
        }
        asm volatile("cp.async.commit_group;");
    };

    for (int t = 0; t < 8; ++t) {
        const int cur = t & 1;
        if (t + 1 < 8) {
            loadC(t + 1, cur ^ 1);
            asm volatile("cp.async.wait_group 1;");
        } else {
            asm volatile("cp.async.wait_group 0;");
        }
        __syncthreads();
        const float* bs = Bs + cur * HF * STR;
        const int kb = t * BK;
        #pragma unroll
        for (int ks = 0; ks < 2; ++ks) {
            uint32_t af[MF][4], bf[NF][2];
            #pragma unroll
            for (int mf = 0; mf < MF; ++mf) {
                int r0 = (wy * 64 + mf * 16 + g) * STR2 + kb + ks * 8 + tg;
                af[mf][0] = __float_as_uint(h1s[r0]);
                af[mf][1] = __float_as_uint(h1s[r0 + 8 * STR2]);
                af[mf][2] = __float_as_uint(h1s[r0 + 4]);
                af[mf][3] = __float_as_uint(h1s[r0 + 8 * STR2 + 4]);
            }
            #pragma unroll
            for (int nf = 0; nf < NF; ++nf) {
                int rb = (wx * WTN + nf * 8 + g) * STR + ks * 8 + tg;
                bf[nf][0] = rnau(bs[rb]);
                bf[nf][1] = rnau(bs[rb + 4]);
            }
            #pragma unroll
            for (int mf = 0; mf < MF; ++mf)
                #pragma unroll
                for (int nf = 0; nf < NF; ++nf)
                    MMA_TF32(acc[mf][nf], af[mf], bf[nf]);
        }
        __syncthreads();
    }

    // stage-C epilogue: relu + store g_t + fused BN stats
    #pragma unroll
    for (int nf = 0; nf < NF; ++nf) {
        int n0 = wx * WTN + nf * 8 + tg * 2;
        float b0 = bf1[n0], b1 = bf1[n0 + 1];
        float ps0 = 0.f, pq0 = 0.f, ps1 = 0.f, pq1 = 0.f;
        #pragma unroll
        for (int mf = 0; mf < MF; ++mf) {
            #pragma unroll
            for (int half = 0; half < 2; ++half) {
                int m = bm + wy * 64 + mf * 16 + g + half * 8;
                if (m >= NN) continue;
                float v0 = fmaxf(acc[mf][nf][half * 2 + 0] + b0, 0.f);
                float v1 = fmaxf(acc[mf][nf][half * 2 + 1] + b1, 0.f);
                *(float2*)(g_t + (size_t)m * HF + n0) = make_float2(v0, v1);
                ps0 += v0; pq0 += v0 * v0; ps1 += v1; pq1 += v1 * v1;
            }
        }
        #pragma unroll
        for (int msk = 16; msk >= 4; msk >>= 1) {
            ps0 += __shfl_xor_sync(0xffffffffu, ps0, msk);
            pq0 += __shfl_xor_sync(0xffffffffu, pq0, msk);
            ps1 += __shfl_xor_sync(0xffffffffu, ps1, msk);
            pq1 += __shfl_xor_sync(0xffffffffu, pq1, msk);
        }
        if (g == 0) {
            atomicAdd(&s_sum[n0],     ps0); atomicAdd(&s_sq[n0],     pq0);
            atomicAdd(&s_sum[n0 + 1], ps1); atomicAdd(&s_sq[n0 + 1], pq1);
        }
    }
    __syncthreads();
    if (tid < HF) {
        atomicAdd(&g_sum[tid],   s_sum[tid]);
        atomicAdd(&g_sumsq[tid], s_sq[tid]);
    }
}

// ---------------- fold BN affine into Wf2/bf2 --------------------------------
__global__ void k_fold(const float* __restrict__ gamma, const float* __restrict__ beta,
                       const float* __restrict__ Wf2,   const float* __restrict__ bf2,
                       int M) {
    __shared__ float a[HF], b[HF];
    int t = threadIdx.x;
    if (t < HF) {
        float inv  = 1.f / (float)M;
        float mean = g_sum[t] * inv;
        float var  = g_sumsq[t] * inv - mean * mean;
        float av   = gamma[t] * rsqrtf(var + 1e-5f);
        a[t] = av;
        b[t] = beta[t] - mean * av;
    }
    __syncthreads();
    for (int i = t; i < OF * HF; i += blockDim.x)
        g_Wf2p[i] = Wf2[i] * a[i & (HF - 1)];
    if (t < OF) {
        float s = bf2[t];
        for (int h = 0; h < HF; ++h) s += b[h] * Wf2[t * HF + h];
        g_bf2p[t] = s;
    }
}

// -----------------------------------------------------------------------------
extern "C" void kernel_launch(void* const* d_in, const int* in_sizes, int n_in,
                              void* d_out, int out_size) {
    const float* x     = (const float*)d_in[0];
    const int*   ei    = (const int*)  d_in[1];
    const float* WA    = (const float*)d_in[2];
    const float* bA    = (const float*)d_in[3];
    const float* WX    = (const float*)d_in[4];
    const float* bX    = (const float*)d_in[5];
    const float* W     = (const float*)d_in[6];
    const float* bW    = (const float*)d_in[7];
    const float* Wf1   = (const float*)d_in[8];
    const float* bf1   = (const float*)d_in[9];
    const float* gamma = (const float*)d_in[10];
    const float* beta  = (const float*)d_in[11];
    const float* Wf2   = (const float*)d_in[12];
    const float* bf2   = (const float*)d_in[13];
    float* out = (float*)d_out;

    const int E = in_sizes[1] / 2;
    const int M = NN;
    const int* row = ei;
    const int* col = ei + E;

    float *pCat, *pT, *pW2, *pB2;
    cudaGetSymbolAddress((void**)&pCat, g_cat);
    cudaGetSymbolAddress((void**)&pT,   g_t);
    cudaGetSymbolAddress((void**)&pW2,  g_Wf2p);
    cudaGetSymbolAddress((void**)&pB2,  g_bf2p);

    static int inited = 0;
    static cudaStream_t sT, sG;            // transpose stream, GEMM1 stream
    static cudaEvent_t evRoot, evT, evG;
    if (!inited) {
        cudaFuncSetAttribute(k_mm23, cudaFuncAttributeMaxDynamicSharedMemorySize,
                             MM23_BYTES);
        cudaStreamCreateWithFlags(&sT, cudaStreamNonBlocking);
        cudaStreamCreateWithFlags(&sG, cudaStreamNonBlocking);
        cudaEventCreateWithFlags(&evRoot, cudaEventDisableTiming);
        cudaEventCreateWithFlags(&evT,    cudaEventDisableTiming);
        cudaEventCreateWithFlags(&evG,    cudaEventDisableTiming);
        inited = 1;
    }

    // ---- fork: secondary streams branch off stream 0 ------------------------
    cudaEventRecord(evRoot, 0);
    cudaStreamWaitEvent(sT, evRoot, 0);
    cudaStreamWaitEvent(sG, evRoot, 0);

    // stream sT: transpose WA (independent of edge binning)
    k_transpose<<<dim3((NN + 31) / 32, HF / 32), dim3(32, 8), 0, sT>>>(WA);
    cudaEventRecord(evT, sT);

    // stream sG: GEMM1  xX = x @ WX^T + bX -> cat[:, 128:]  (independent)
    k_mm<128, 0, 1><<<GBLK, 256, 0, sG>>>(x, INF, WX, bX, pCat + HF, 2 * HF, INF);
    cudaEventRecord(evG, sG);

    // stream 0: edge pipeline
    k_init<<<(NN + 255) / 256, 256>>>();
    k_hist<<<(E / 4 + 255) / 256, 256>>>(row, E);
    k_scan<<<1, 1024>>>(E);
    k_bin<<<(E / 4 + 255) / 256, 256>>>(row, col, E);

    // join transpose, then gather (writes cat[:, :128])
    cudaStreamWaitEvent(0, evT, 0);
    k_gather<<<(NN * 32 + 255) / 256, 256>>>(bA);

    // join GEMM1, then fused GEMM2+3
    cudaStreamWaitEvent(0, evG, 0);
    k_mm23<<<GBLK, 256, MM23_BYTES>>>(W, bW, Wf1, bf1);

    // fold BN, final GEMM
    k_fold<<<1, 256>>>(gamma, beta, Wf2, bf2, M);
    k_mm<64, 0, 0><<<GBLK, 256>>>(pT, HF, pW2, pB2, out, OF, HF);
}

// round 12
// speedup vs baseline: 1.5401x; 1.3231x over previous
#include <cuda_runtime.h>
#include <cstdint>

#define NN   50000
#define NP   50048            // padded rows = 391 * 128
#define EE   800000
#define INF  512
#define HF   128
#define OF   64
#define GBLK 391              // ceil(50000/128)
#define SCB  196              // scan blocks: ceil(50000/256)

// ---------------- scratch (static device globals; zero-initialized) ---------
__device__ float g_WAT [(size_t)NN * HF];      // WA transposed: [N, H]
__device__ float g_cat [(size_t)NP * 2 * HF];  // [NP, 256] (xA | xX); tail rows stay 0
__device__ float g_t   [(size_t)NP * HF];
__device__ float g_Wf2p[OF * HF];              // BN-folded
__device__ float g_bf2p[OF];
__device__ int   g_hist[NN];
__device__ int   g_off [NN + 1];
__device__ int   g_cur [NN];
__device__ int   g_dst [EE];
__device__ int   g_bsum[SCB];
__device__ int   g_boff[SCB];
__device__ int   g_rmin;
__device__ float g_sum  [HF];
__device__ float g_sumsq[HF];

// ---------------- helpers ----------------------------------------------------
__device__ __forceinline__ float rna(float f) {
    float r; asm("cvt.rna.tf32.f32 %0, %1;" : "=f"(r) : "f"(f)); return r;
}
__device__ __forceinline__ uint32_t rnau(float f) { return __float_as_uint(rna(f)); }
__device__ __forceinline__ uint32_t s2u(const void* p) {
    uint32_t a;
    asm("{ .reg .u64 t; cvta.to.shared.u64 t, %1; cvt.u32.u64 %0, t; }" : "=r"(a) : "l"(p));
    return a;
}
__device__ __forceinline__ void cp16(uint32_t d, const void* s) {
    asm volatile("cp.async.cg.shared.global [%0], [%1], 16;" :: "r"(d), "l"(s));
}
__device__ __forceinline__ void cp16z(uint32_t d, const void* s, int sz) {
    asm volatile("cp.async.cg.shared.global [%0], [%1], 16, %2;" :: "r"(d), "l"(s), "r"(sz));
}
#define MMA_TF32(acc, af, bf)                                                 \
    asm volatile(                                                             \
        "mma.sync.aligned.m16n8k8.row.col.f32.tf32.tf32.f32 "                 \
        "{%0,%1,%2,%3},{%4,%5,%6,%7},{%8,%9},{%0,%1,%2,%3};"                  \
        : "+f"((acc)[0]), "+f"((acc)[1]), "+f"((acc)[2]), "+f"((acc)[3])      \
        : "r"((af)[0]), "r"((af)[1]), "r"((af)[2]), "r"((af)[3]),             \
          "r"((bf)[0]), "r"((bf)[1]))

// ---------------- init -------------------------------------------------------
__global__ void k_init() {
    int i = blockIdx.x * blockDim.x + threadIdx.x;
    if (i < NN) g_hist[i] = 0;
    if (blockIdx.x == 0) {
        if (threadIdx.x < HF) { g_sum[threadIdx.x] = 0.f; g_sumsq[threadIdx.x] = 0.f; }
        if (threadIdx.x == 0) g_rmin = 0x7fffffff;
    }
}

// ---------------- histogram + row min (8 edges / thread) ---------------------
__global__ void k_hist(const int* __restrict__ row, int E) {
    int base = (blockIdx.x * blockDim.x + threadIdx.x) * 8;
    int rmn = 0x7fffffff;
    int r[8]; bool ok[8];
    #pragma unroll
    for (int u = 0; u < 8; ++u) {
        int e = base + u;
        ok[u] = e < E;
        if (ok[u]) { r[u] = row[e]; rmn = min(rmn, r[u]); }
    }
    #pragma unroll
    for (int u = 0; u < 8; ++u)
        if (ok[u]) atomicAdd(&g_hist[r[u]], 1);
    unsigned wm = __reduce_min_sync(0xffffffffu, (unsigned)rmn);
    if ((threadIdx.x & 31) == 0) atomicMin(&g_rmin, (int)wm);
}

// ---------------- parallel 3-phase exclusive scan ----------------------------
__global__ void k_scanA() {
    __shared__ int s[256];
    int tid = threadIdx.x;
    int i = blockIdx.x * 256 + tid;
    int v = (i < NN) ? g_hist[i] : 0;
    s[tid] = v;
    __syncthreads();
    #pragma unroll
    for (int ofs = 1; ofs < 256; ofs <<= 1) {
        int t = (tid >= ofs) ? s[tid - ofs] : 0;
        __syncthreads();
        s[tid] += t;
        __syncthreads();
    }
    if (i < NN) g_off[i] = s[tid] - v;          // block-local exclusive
    if (tid == 255) g_bsum[blockIdx.x] = s[255];
}
__global__ void k_scanB() {
    __shared__ int s[256];
    int tid = threadIdx.x;
    int v = (tid < SCB) ? g_bsum[tid] : 0;
    s[tid] = v;
    __syncthreads();
    #pragma unroll
    for (int ofs = 1; ofs < 256; ofs <<= 1) {
        int t = (tid >= ofs) ? s[tid - ofs] : 0;
        __syncthreads();
        s[tid] += t;
        __syncthreads();
    }
    if (tid < SCB) g_boff[tid] = s[tid] - v;
}
__global__ void k_scanC(int E) {
    int i = blockIdx.x * 256 + threadIdx.x;
    if (i < NN) {
        int o = g_off[i] + g_boff[blockIdx.x];
        g_off[i] = o;
        g_cur[i] = o;
    }
    if (i == 0) g_off[NN] = E;
}

// ---------------- bin edges by row (8 edges / thread) ------------------------
__global__ void k_bin(const int* __restrict__ row, const int* __restrict__ col, int E) {
    int base = (blockIdx.x * blockDim.x + threadIdx.x) * 8;
    int r[8], c[8], p[8];
    bool ok[8];
    #pragma unroll
    for (int u = 0; u < 8; ++u) {
        int e = base + u;
        ok[u] = e < E;
        if (ok[u]) { r[u] = row[e]; c[u] = col[e]; }
    }
    #pragma unroll
    for (int u = 0; u < 8; ++u)
        if (ok[u]) p[u] = atomicAdd(&g_cur[r[u]], 1);
    #pragma unroll
    for (int u = 0; u < 8; ++u)
        if (ok[u]) g_dst[p[u]] = c[u];
}

// ---------------- transpose WA [H,N] -> WAT [N,H] ----------------------------
__global__ void k_transpose(const float* __restrict__ WA) {
    __shared__ float tile[32][33];
    int n0 = blockIdx.x * 32, h0 = blockIdx.y * 32;
    int tx = threadIdx.x, ty = threadIdx.y;
    #pragma unroll
    for (int j = 0; j < 32; j += 8) {
        int h = h0 + ty + j, n = n0 + tx;
        tile[ty + j][tx] = (n < NN) ? WA[(size_t)h * NN + n] : 0.f;
    }
    __syncthreads();
    #pragma unroll
    for (int j = 0; j < 32; j += 8) {
        int n = n0 + ty + j, h = h0 + tx;
        if (n < NN) g_WAT[(size_t)n * HF + h] = tile[tx][ty + j];
    }
}

// ---------------- gather xA = segsum(WAT[col]) + bA -> cat[:, :128] ----------
__global__ void k_gather(const float* __restrict__ bA) {
    int w    = (blockIdx.x * blockDim.x + threadIdx.x) >> 5;
    int lane = threadIdx.x & 31;
    if (w >= NN) return;
    int bkt = w + g_rmin;
    int s = 0, e = 0;
    if (bkt < NN) { s = g_off[bkt]; e = g_off[bkt + 1]; }
    float4 acc = *(const float4*)(bA + lane * 4);
    int j = s;
    for (; j + 4 <= e; j += 4) {
        int c0 = g_dst[j], c1 = g_dst[j + 1], c2 = g_dst[j + 2], c3 = g_dst[j + 3];
        float4 v0 = *(const float4*)(g_WAT + (size_t)c0 * HF + lane * 4);
        float4 v1 = *(const float4*)(g_WAT + (size_t)c1 * HF + lane * 4);
        float4 v2 = *(const float4*)(g_WAT + (size_t)c2 * HF + lane * 4);
        float4 v3 = *(const float4*)(g_WAT + (size_t)c3 * HF + lane * 4);
        float4 p, q;
        p.x = v0.x + v1.x; p.y = v0.y + v1.y; p.z = v0.z + v1.z; p.w = v0.w + v1.w;
        q.x = v2.x + v3.x; q.y = v2.y + v3.y; q.z = v2.z + v3.z; q.w = v2.w + v3.w;
        acc.x += p.x + q.x; acc.y += p.y + q.y; acc.z += p.z + q.z; acc.w += p.w + q.w;
    }
    for (; j < e; ++j) {
        int c = g_dst[j];
        float4 v = *(const float4*)(g_WAT + (size_t)c * HF + lane * 4);
        acc.x += v.x; acc.y += v.y; acc.z += v.z; acc.w += v.w;
    }
    *((float4*)(g_cat + (size_t)w * (2 * HF) + lane * 4)) = acc;
}

// ---------------- tf32 mma.sync GEMM (2-stage) -------------------------------
template<int BN, int EPI, int GUARD>
__global__ __launch_bounds__(256)
void k_mm(const float* __restrict__ A, int lda,
          const float* __restrict__ B,
          const float* __restrict__ bias,
          float* __restrict__ C, int ldc, int K)
{
    constexpr int BM = 128, BK = 16, STR = 20;
    constexpr int WXn = 4, WTN = BN / WXn;
    constexpr int NF = WTN / 8;
    constexpr int MF = 4;
    __shared__ __align__(16) float As[2][BM * STR];
    __shared__ __align__(16) float Bs[2][BN * STR];

    const int tid  = threadIdx.x;
    const int lane = tid & 31, warp = tid >> 5;
    const int wy = warp / WXn, wx = warp % WXn;
    const int g = lane >> 2, tg = lane & 3;
    const int bm = blockIdx.x * BM;

    float acc[MF][NF][4];
    #pragma unroll
    for (int i = 0; i < MF; ++i)
        #pragma unroll
        for (int j = 0; j < NF; ++j)
            #pragma unroll
            for (int c = 0; c < 4; ++c) acc[i][j][c] = 0.f;

    const uint32_t aS = s2u(As), bS = s2u(Bs);
    const int T = K / BK;

    auto load_tiles = [&](int t, int st) {
        const int k0 = t * BK;
        #pragma unroll
        for (int i = 0; i < BM * 4 / 256; ++i) {
            int idx = tid + i * 256;
            int r = idx >> 2, ch = idx & 3;
            uint32_t d = aS + (uint32_t)(st * BM * STR + r * STR + ch * 4) * 4;
            if (GUARD) {
                bool v = (bm + r) < NN;
                cp16z(d, A + (v ? ((size_t)(bm + r) * lda + k0 + ch * 4) : 0), v ? 16 : 0);
            } else {
                cp16(d, A + (size_t)(bm + r) * lda + k0 + ch * 4);
            }
        }
        #pragma unroll
        for (int i = 0; i < BN * 4 / 256; ++i) {
            int idx = tid + i * 256;
            int r = idx >> 2, ch = idx & 3;
            cp16(bS + (uint32_t)(st * BN * STR + r * STR + ch * 4) * 4,
                 B + (size_t)r * K + k0 + ch * 4);
        }
        asm volatile("cp.async.commit_group;");
    };

    load_tiles(0, 0);

    for (int t = 0; t < T; ++t) {
        const int cur = t & 1;
        if (t + 1 < T) {
            load_tiles(t + 1, cur ^ 1);
            asm volatile("cp.async.wait_group 1;");
        } else {
            asm volatile("cp.async.wait_group 0;");
        }
        __syncthreads();

        const float* as = As[cur];
        const float* bs = Bs[cur];
        #pragma unroll
        for (int ks = 0; ks < 2; ++ks) {
            uint32_t af[MF][4], bf[NF][2];
            #pragma unroll
            for (int mf = 0; mf < MF; ++mf) {
                int r0 = (wy * 64 + mf * 16 + g) * STR + ks * 8 + tg;
                af[mf][0] = rnau(as[r0]);
                af[mf][1] = rnau(as[r0 + 8 * STR]);
                af[mf][2] = rnau(as[r0 + 4]);
                af[mf][3] = rnau(as[r0 + 8 * STR + 4]);
            }
            #pragma unroll
            for (int nf = 0; nf < NF; ++nf) {
                int rb = (wx * WTN + nf * 8 + g) * STR + ks * 8 + tg;
                bf[nf][0] = rnau(bs[rb]);
                bf[nf][1] = rnau(bs[rb + 4]);
            }
            #pragma unroll
            for (int mf = 0; mf < MF; ++mf)
                #pragma unroll
                for (int nf = 0; nf < NF; ++nf)
                    MMA_TF32(acc[mf][nf], af[mf], bf[nf]);
        }
        __syncthreads();
    }

    #pragma unroll
    for (int nf = 0; nf < NF; ++nf) {
        int n0 = wx * WTN + nf * 8 + tg * 2;
        float b0 = bias[n0], b1 = bias[n0 + 1];
        #pragma unroll
        for (int mf = 0; mf < MF; ++mf) {
            #pragma unroll
            for (int half = 0; half < 2; ++half) {
                int m = bm + wy * 64 + mf * 16 + g + half * 8;
                if (m >= NN) continue;
                float v0 = acc[mf][nf][half * 2 + 0] + b0;
                float v1 = acc[mf][nf][half * 2 + 1] + b1;
                if (EPI == 2) { v0 = fmaxf(v0, 0.f); v1 = fmaxf(v1, 0.f); }
                *(float2*)(C + (size_t)m * ldc + n0) = make_float2(v0, v1);
            }
        }
    }
}

// ---------------- fused GEMM2+GEMM3 (dynamic smem) ---------------------------
#define MM23_AS     0
#define MM23_BS     (2 * 128 * 20)
#define MM23_H1     (4 * 128 * 20)
#define MM23_FLOATS (MM23_H1 + 128 * 132)
#define MM23_BYTES  (MM23_FLOATS * 4)

__global__ __launch_bounds__(256)
void k_mm23(const float* __restrict__ W,   const float* __restrict__ bW,
            const float* __restrict__ Wf1, const float* __restrict__ bf1)
{
    constexpr int BM = 128, BK = 16, STR = 20, STR2 = 132;
    constexpr int WXn = 4, WTN = 32, NF = 4, MF = 4;
    extern __shared__ float dyn[];
    float* As  = dyn + MM23_AS;
    float* Bs  = dyn + MM23_BS;
    float* h1s = dyn + MM23_H1;
    __shared__ float s_sum[HF], s_sq[HF];

    const int tid  = threadIdx.x;
    const int lane = tid & 31, warp = tid >> 5;
    const int wy = warp / WXn, wx = warp % WXn;
    const int g = lane >> 2, tg = lane & 3;
    const int bm = blockIdx.x * BM;
    const float* cat = g_cat;

    if (tid < HF) { s_sum[tid] = 0.f; s_sq[tid] = 0.f; }

    float acc[MF][NF][4];
    #pragma unroll
    for (int i = 0; i < MF; ++i)
        #pragma unroll
        for (int j = 0; j < NF; ++j)
            #pragma unroll
            for (int c = 0; c < 4; ++c) acc[i][j][c] = 0.f;

    const uint32_t aS = s2u(As), bS = s2u(Bs);

    auto loadB = [&](int t, int st) {
        const int k0 = t * BK;
        #pragma unroll
        for (int i = 0; i < 2; ++i) {
            int idx = tid + i * 256;
            int r = idx >> 2, ch = idx & 3;
            cp16(aS + (uint32_t)(st * BM * STR + r * STR + ch * 4) * 4,
                 cat + (size_t)(bm + r) * 256 + k0 + ch * 4);
        }
        #pragma unroll
        for (int i = 0; i < 2; ++i) {
            int idx = tid + i * 256;
            int r = idx >> 2, ch = idx & 3;
            cp16(bS + (uint32_t)(st * HF * STR + r * STR + ch * 4) * 4,
                 W + (size_t)r * 256 + k0 + ch * 4);
        }
        asm volatile("cp.async.commit_group;");
    };

    loadB(0, 0);
    for (int t = 0; t < 16; ++t) {
        const int cur = t & 1;
        if (t + 1 < 16) {
            loadB(t + 1, cur ^ 1);
            asm volatile("cp.async.wait_group 1;");
        } else {
            asm volatile("cp.async.wait_group 0;");
        }
        __syncthreads();
        const float* as = As + cur * BM * STR;
        const float* bs = Bs + cur * HF * STR;
        #pragma unroll
        for (int ks = 0; ks < 2; ++ks) {
            uint32_t af[MF][4], bf[NF][2];
            #pragma unroll
            for (int mf = 0; mf < MF; ++mf) {
                int r0 = (wy * 64 + mf * 16 + g) * STR + ks * 8 + tg;
                af[mf][0] = rnau(as[r0]);
                af[mf][1] = rnau(as[r0 + 8 * STR]);
                af[mf][2] = rnau(as[r0 + 4]);
                af[mf][3] = rnau(as[r0 + 8 * STR + 4]);
            }
            #pragma unroll
            for (int nf = 0; nf < NF; ++nf) {
                int rb = (wx * WTN + nf * 8 + g) * STR + ks * 8 + tg;
                bf[nf][0] = rnau(bs[rb]);
                bf[nf][1] = rnau(bs[rb + 4]);
            }
            #pragma unroll
            for (int mf = 0; mf < MF; ++mf)
                #pragma unroll
                for (int nf = 0; nf < NF; ++nf)
                    MMA_TF32(acc[mf][nf], af[mf], bf[nf]);
        }
        __syncthreads();
    }

    // prefetch stage-C B tile 0 (Wf1)
    {
        #pragma unroll
        for (int i = 0; i < 2; ++i) {
            int idx = tid + i * 256;
            int r = idx >> 2, ch = idx & 3;
            cp16(bS + (uint32_t)(r * STR + ch * 4) * 4,
                 Wf1 + (size_t)r * HF + ch * 4);
        }
        asm volatile("cp.async.commit_group;");
    }

    // stage-B epilogue: skip + relu + rna -> h1s
    #pragma unroll
    for (int nf = 0; nf < NF; ++nf) {
        int n0 = wx * WTN + nf * 8 + tg * 2;
        float b0 = bW[n0], b1 = bW[n0 + 1];
        #pragma unroll
        for (int mf = 0; mf < MF; ++mf) {
            #pragma unroll
            for (int half = 0; half < 2; ++half) {
                int ml = wy * 64 + mf * 16 + g + half * 8;
                const float* sp = cat + (size_t)(bm + ml) * 256;
                float v0 = acc[mf][nf][half * 2 + 0] + b0 + sp[n0]     + sp[128 + n0];
                float v1 = acc[mf][nf][half * 2 + 1] + b1 + sp[n0 + 1] + sp[128 + n0 + 1];
                v0 = rna(fmaxf(v0, 0.f)); v1 = rna(fmaxf(v1, 0.f));
                *(float2*)(h1s + ml * STR2 + n0) = make_float2(v0, v1);
                acc[mf][nf][half * 2 + 0] = 0.f;
                acc[mf][nf][half * 2 + 1] = 0.f;
            }
        }
    }
    __syncthreads();

    // stage C: K = 128, A from h1s, B = Wf1
    auto loadC = [&](int t, int st) {
        const int k0 = t * BK;
        #pragma unroll
        for (int i = 0; i < 2; ++i) {
            int idx = tid + i * 256;
            int r = idx >> 2, ch = idx & 3;
            cp16(bS + (uint32_t)(st * HF * STR + r * STR + ch * 4) * 4,
                 Wf1 + (size_t)r * HF + k0 + ch * 4);
        }
        asm volatile("cp.async.commit_group;");
    };

    for (int t = 0; t < 8; ++t) {
        const int cur = t & 1;
        if (t + 1 < 8) {
            loadC(t + 1, cur ^ 1);
            asm volatile("cp.async.wait_group 1;");
        } else {
            asm volatile("cp.async.wait_group 0;");
        }
        __syncthreads();
        const float* bs = Bs + cur * HF * STR;
        const int kb = t * BK;
        #pragma unroll
        for (int ks = 0; ks < 2; ++ks) {
            uint32_t af[MF][4], bf[NF][2];
            #pragma unroll
            for (int mf = 0; mf < MF; ++mf) {
                int r0 = (wy * 64 + mf * 16 + g) * STR2 + kb + ks * 8 + tg;
                af[mf][0] = __float_as_uint(h1s[r0]);
                af[mf][1] = __float_as_uint(h1s[r0 + 8 * STR2]);
                af[mf][2] = __float_as_uint(h1s[r0 + 4]);
                af[mf][3] = __float_as_uint(h1s[r0 + 8 * STR2 + 4]);
            }
            #pragma unroll
            for (int nf = 0; nf < NF; ++nf) {
                int rb = (wx * WTN + nf * 8 + g) * STR + ks * 8 + tg;
                bf[nf][0] = rnau(bs[rb]);
                bf[nf][1] = rnau(bs[rb + 4]);
            }
            #pragma unroll
            for (int mf = 0; mf < MF; ++mf)
                #pragma unroll
                for (int nf = 0; nf < NF; ++nf)
                    MMA_TF32(acc[mf][nf], af[mf], bf[nf]);
        }
        __syncthreads();
    }

    // stage-C epilogue: relu + store g_t + fused BN stats
    #pragma unroll
    for (int nf = 0; nf < NF; ++nf) {
        int n0 = wx * WTN + nf * 8 + tg * 2;
        float b0 = bf1[n0], b1 = bf1[n0 + 1];
        float ps0 = 0.f, pq0 = 0.f, ps1 = 0.f, pq1 = 0.f;
        #pragma unroll
        for (int mf = 0; mf < MF; ++mf) {
            #pragma unroll
            for (int half = 0; half < 2; ++half) {
                int m = bm + wy * 64 + mf * 16 + g + half * 8;
                if (m >= NN) continue;
                float v0 = fmaxf(acc[mf][nf][half * 2 + 0] + b0, 0.f);
                float v1 = fmaxf(acc[mf][nf][half * 2 + 1] + b1, 0.f);
                *(float2*)(g_t + (size_t)m * HF + n0) = make_float2(v0, v1);
                ps0 += v0; pq0 += v0 * v0; ps1 += v1; pq1 += v1 * v1;
            }
        }
        #pragma unroll
        for (int msk = 16; msk >= 4; msk >>= 1) {
            ps0 += __shfl_xor_sync(0xffffffffu, ps0, msk);
            pq0 += __shfl_xor_sync(0xffffffffu, pq0, msk);
            ps1 += __shfl_xor_sync(0xffffffffu, ps1, msk);
            pq1 += __shfl_xor_sync(0xffffffffu, pq1, msk);
        }
        if (g == 0) {
            atomicAdd(&s_sum[n0],     ps0); atomicAdd(&s_sq[n0],     pq0);
            atomicAdd(&s_sum[n0 + 1], ps1); atomicAdd(&s_sq[n0 + 1], pq1);
        }
    }
    __syncthreads();
    if (tid < HF) {
        atomicAdd(&g_sum[tid],   s_sum[tid]);
        atomicAdd(&g_sumsq[tid], s_sq[tid]);
    }
}

// ---------------- fold BN affine into Wf2/bf2 --------------------------------
__global__ void k_fold(const float* __restrict__ gamma, const float* __restrict__ beta,
                       const float* __restrict__ Wf2,   const float* __restrict__ bf2,
                       int M) {
    __shared__ float a[HF], b[HF];
    int t = threadIdx.x;
    if (t < HF) {
        float inv  = 1.f / (float)M;
        float mean = g_sum[t] * inv;
        float var  = g_sumsq[t] * inv - mean * mean;
        float av   = gamma[t] * rsqrtf(var + 1e-5f);
        a[t] = av;
        b[t] = beta[t] - mean * av;
    }
    __syncthreads();
    for (int i = t; i < OF * HF; i += blockDim.x)
        g_Wf2p[i] = Wf2[i] * a[i & (HF - 1)];
    if (t < OF) {
        float s = bf2[t];
        for (int h = 0; h < HF; ++h) s += b[h] * Wf2[t * HF + h];
        g_bf2p[t] = s;
    }
}

// -----------------------------------------------------------------------------
extern "C" void kernel_launch(void* const* d_in, const int* in_sizes, int n_in,
                              void* d_out, int out_size) {
    const float* x     = (const float*)d_in[0];
    const int*   ei    = (const int*)  d_in[1];
    const float* WA    = (const float*)d_in[2];
    const float* bA    = (const float*)d_in[3];
    const float* WX    = (const float*)d_in[4];
    const float* bX    = (const float*)d_in[5];
    const float* W     = (const float*)d_in[6];
    const float* bW    = (const float*)d_in[7];
    const float* Wf1   = (const float*)d_in[8];
    const float* bf1   = (const float*)d_in[9];
    const float* gamma = (const float*)d_in[10];
    const float* beta  = (const float*)d_in[11];
    const float* Wf2   = (const float*)d_in[12];
    const float* bf2   = (const float*)d_in[13];
    float* out = (float*)d_out;

    const int E = in_sizes[1] / 2;
    const int M = NN;
    const int* row = ei;
    const int* col = ei + E;

    float *pCat, *pT, *pW2, *pB2;
    cudaGetSymbolAddress((void**)&pCat, g_cat);
    cudaGetSymbolAddress((void**)&pT,   g_t);
    cudaGetSymbolAddress((void**)&pW2,  g_Wf2p);
    cudaGetSymbolAddress((void**)&pB2,  g_bf2p);

    static int inited = 0;
    static cudaStream_t sT, sG;
    static cudaEvent_t evRoot, evT, evG;
    if (!inited) {
        cudaFuncSetAttribute(k_mm23, cudaFuncAttributeMaxDynamicSharedMemorySize,
                             MM23_BYTES);
        cudaStreamCreateWithFlags(&sT, cudaStreamNonBlocking);
        cudaStreamCreateWithFlags(&sG, cudaStreamNonBlocking);
        cudaEventCreateWithFlags(&evRoot, cudaEventDisableTiming);
        cudaEventCreateWithFlags(&evT,    cudaEventDisableTiming);
        cudaEventCreateWithFlags(&evG,    cudaEventDisableTiming);
        inited = 1;
    }

    // ---- fork -----------------------------------------------------------------
    cudaEventRecord(evRoot, 0);
    cudaStreamWaitEvent(sT, evRoot, 0);
    cudaStreamWaitEvent(sG, evRoot, 0);

    // stream sT: transpose WA
    k_transpose<<<dim3((NN + 31) / 32, HF / 32), dim3(32, 8), 0, sT>>>(WA);
    cudaEventRecord(evT, sT);

    // stream sG: GEMM1  xX = x @ WX^T + bX -> cat[:, 128:]
    k_mm<128, 0, 1><<<GBLK, 256, 0, sG>>>(x, INF, WX, bX, pCat + HF, 2 * HF, INF);
    cudaEventRecord(evG, sG);

    // stream 0: edge pipeline
    k_init<<<(NN + 255) / 256, 256>>>();
    k_hist<<<(E / 8 + 255) / 256, 256>>>(row, E);
    k_scanA<<<SCB, 256>>>();
    k_scanB<<<1, 256>>>();
    k_scanC<<<SCB, 256>>>(E);
    k_bin<<<(E / 8 + 255) / 256, 256>>>(row, col, E);

    // join transpose, then gather
    cudaStreamWaitEvent(0, evT, 0);
    k_gather<<<(NN * 32 + 255) / 256, 256>>>(bA);

    // join GEMM1, then fused GEMM2+3
    cudaStreamWaitEvent(0, evG, 0);
    k_mm23<<<GBLK, 256, MM23_BYTES>>>(W, bW, Wf1, bf1);

    // fold BN, final GEMM
    k_fold<<<1, 256>>>(gamma, beta, Wf2, bf2, M);
    k_mm<64, 0, 0><<<GBLK, 256>>>(pT, HF, pW2, pB2, out, OF, HF);
}

// round 13
// speedup vs baseline: 1.5561x; 1.0104x over previous
#include <cuda_runtime.h>
#include <cstdint>

#define NN   50000
#define NP   50048            // padded rows = 391 * 128
#define EE   800000
#define INF  512
#define HF   128
#define OF   64
#define GBLK 391              // ceil(50000/128)
#define SCB  196              // scan blocks: ceil(50000/256)

// ---------------- scratch (static device globals; zero-initialized) ---------
__device__ float g_WAT [(size_t)NN * HF];      // WA transposed: [N, H]
__device__ float g_cat [(size_t)NP * 2 * HF];  // [NP, 256] (xA | xX), pre-rounded
__device__ float g_t   [(size_t)NP * HF];      // pre-rounded
__device__ float g_WXr [HF * INF];             // rna-rounded weights
__device__ float g_Wr  [HF * 2 * HF];
__device__ float g_Wf1r[HF * HF];
__device__ float g_Wf2p[OF * HF];              // BN-folded + rounded
__device__ float g_bf2p[OF];
__device__ int   g_hist[NN];
__device__ int   g_off [NN + 1];
__device__ int   g_cur [NN];
__device__ int   g_dst [EE];
__device__ int   g_bsum[SCB];
__device__ int   g_boff[SCB];
__device__ int   g_rmin;
__device__ float g_sum  [HF];
__device__ float g_sumsq[HF];

// ---------------- helpers ----------------------------------------------------
__device__ __forceinline__ float rna(float f) {
    float r; asm("cvt.rna.tf32.f32 %0, %1;" : "=f"(r) : "f"(f)); return r;
}
__device__ __forceinline__ uint32_t rnau(float f) { return __float_as_uint(rna(f)); }
__device__ __forceinline__ uint32_t s2u(const void* p) {
    uint32_t a;
    asm("{ .reg .u64 t; cvta.to.shared.u64 t, %1; cvt.u32.u64 %0, t; }" : "=r"(a) : "l"(p));
    return a;
}
__device__ __forceinline__ void cp16(uint32_t d, const void* s) {
    asm volatile("cp.async.cg.shared.global [%0], [%1], 16;" :: "r"(d), "l"(s));
}
__device__ __forceinline__ void cp16z(uint32_t d, const void* s, int sz) {
    asm volatile("cp.async.cg.shared.global [%0], [%1], 16, %2;" :: "r"(d), "l"(s), "r"(sz));
}
#define MMA_TF32(acc, af, bf)                                                 \
    asm volatile(                                                             \
        "mma.sync.aligned.m16n8k8.row.col.f32.tf32.tf32.f32 "                 \
        "{%0,%1,%2,%3},{%4,%5,%6,%7},{%8,%9},{%0,%1,%2,%3};"                  \
        : "+f"((acc)[0]), "+f"((acc)[1]), "+f"((acc)[2]), "+f"((acc)[3])      \
        : "r"((af)[0]), "r"((af)[1]), "r"((af)[2]), "r"((af)[3]),             \
          "r"((bf)[0]), "r"((bf)[1]))

// ---------------- init -------------------------------------------------------
__global__ void k_init() {
    int i = blockIdx.x * blockDim.x + threadIdx.x;
    if (i < NN) g_hist[i] = 0;
    if (blockIdx.x == 0) {
        if (threadIdx.x < HF) { g_sum[threadIdx.x] = 0.f; g_sumsq[threadIdx.x] = 0.f; }
        if (threadIdx.x == 0) g_rmin = 0x7fffffff;
    }
}

// ---------------- round weights (side stream, off critical path) -------------
__global__ void k_roundw(const float* __restrict__ WX, const float* __restrict__ W,
                         const float* __restrict__ Wf1) {
    int i = blockIdx.x * blockDim.x + threadIdx.x;
    if (i < HF * INF)    g_WXr[i]  = rna(WX[i]);
    if (i < HF * 2 * HF) g_Wr[i]   = rna(W[i]);
    if (i < HF * HF)     g_Wf1r[i] = rna(Wf1[i]);
}

// ---------------- histogram + row min (8 edges / thread) ---------------------
__global__ void k_hist(const int* __restrict__ row, int E) {
    int base = (blockIdx.x * blockDim.x + threadIdx.x) * 8;
    int rmn = 0x7fffffff;
    int r[8]; bool ok[8];
    #pragma unroll
    for (int u = 0; u < 8; ++u) {
        int e = base + u;
        ok[u] = e < E;
        if (ok[u]) { r[u] = row[e]; rmn = min(rmn, r[u]); }
    }
    #pragma unroll
    for (int u = 0; u < 8; ++u)
        if (ok[u]) atomicAdd(&g_hist[r[u]], 1);
    unsigned wm = __reduce_min_sync(0xffffffffu, (unsigned)rmn);
    if ((threadIdx.x & 31) == 0) atomicMin(&g_rmin, (int)wm);
}

// ---------------- parallel 3-phase exclusive scan ----------------------------
__global__ void k_scanA() {
    __shared__ int s[256];
    int tid = threadIdx.x;
    int i = blockIdx.x * 256 + tid;
    int v = (i < NN) ? g_hist[i] : 0;
    s[tid] = v;
    __syncthreads();
    #pragma unroll
    for (int ofs = 1; ofs < 256; ofs <<= 1) {
        int t = (tid >= ofs) ? s[tid - ofs] : 0;
        __syncthreads();
        s[tid] += t;
        __syncthreads();
    }
    if (i < NN) g_off[i] = s[tid] - v;
    if (tid == 255) g_bsum[blockIdx.x] = s[255];
}
__global__ void k_scanB() {
    __shared__ int s[256];
    int tid = threadIdx.x;
    int v = (tid < SCB) ? g_bsum[tid] : 0;
    s[tid] = v;
    __syncthreads();
    #pragma unroll
    for (int ofs = 1; ofs < 256; ofs <<= 1) {
        int t = (tid >= ofs) ? s[tid - ofs] : 0;
        __syncthreads();
        s[tid] += t;
        __syncthreads();
    }
    if (tid < SCB) g_boff[tid] = s[tid] - v;
}
__global__ void k_scanC(int E) {
    int i = blockIdx.x * 256 + threadIdx.x;
    if (i < NN) {
        int o = g_off[i] + g_boff[blockIdx.x];
        g_off[i] = o;
        g_cur[i] = o;
    }
    if (i == 0) g_off[NN] = E;
}

// ---------------- bin edges by row (8 edges / thread) ------------------------
__global__ void k_bin(const int* __restrict__ row, const int* __restrict__ col, int E) {
    int base = (blockIdx.x * blockDim.x + threadIdx.x) * 8;
    int r[8], c[8], p[8];
    bool ok[8];
    #pragma unroll
    for (int u = 0; u < 8; ++u) {
        int e = base + u;
        ok[u] = e < E;
        if (ok[u]) { r[u] = row[e]; c[u] = col[e]; }
    }
    #pragma unroll
    for (int u = 0; u < 8; ++u)
        if (ok[u]) p[u] = atomicAdd(&g_cur[r[u]], 1);
    #pragma unroll
    for (int u = 0; u < 8; ++u)
        if (ok[u]) g_dst[p[u]] = c[u];
}

// ---------------- transpose WA [H,N] -> WAT [N,H] ----------------------------
__global__ void k_transpose(const float* __restrict__ WA) {
    __shared__ float tile[32][33];
    int n0 = blockIdx.x * 32, h0 = blockIdx.y * 32;
    int tx = threadIdx.x, ty = threadIdx.y;
    #pragma unroll
    for (int j = 0; j < 32; j += 8) {
        int h = h0 + ty + j, n = n0 + tx;
        tile[ty + j][tx] = (n < NN) ? WA[(size_t)h * NN + n] : 0.f;
    }
    __syncthreads();
    #pragma unroll
    for (int j = 0; j < 32; j += 8) {
        int n = n0 + ty + j, h = h0 + tx;
        if (n < NN) g_WAT[(size_t)n * HF + h] = tile[tx][ty + j];
    }
}

// ---------------- gather xA = segsum(WAT[col]) + bA -> cat[:, :128] ----------
__global__ void k_gather(const float* __restrict__ bA) {
    int w    = (blockIdx.x * blockDim.x + threadIdx.x) >> 5;
    int lane = threadIdx.x & 31;
    if (w >= NN) return;
    int bkt = w + g_rmin;
    int s = 0, e = 0;
    if (bkt < NN) { s = g_off[bkt]; e = g_off[bkt + 1]; }
    float4 acc = *(const float4*)(bA + lane * 4);
    int j = s;
    for (; j + 8 <= e; j += 8) {
        int cc[8];
        #pragma unroll
        for (int u = 0; u < 8; ++u) cc[u] = g_dst[j + u];
        float4 v[8];
        #pragma unroll
        for (int u = 0; u < 8; ++u)
            v[u] = *(const float4*)(g_WAT + (size_t)cc[u] * HF + lane * 4);
        float4 p0, p1, p2, p3;
        p0.x = v[0].x + v[1].x; p0.y = v[0].y + v[1].y; p0.z = v[0].z + v[1].z; p0.w = v[0].w + v[1].w;
        p1.x = v[2].x + v[3].x; p1.y = v[2].y + v[3].y; p1.z = v[2].z + v[3].z; p1.w = v[2].w + v[3].w;
        p2.x = v[4].x + v[5].x; p2.y = v[4].y + v[5].y; p2.z = v[4].z + v[5].z; p2.w = v[4].w + v[5].w;
        p3.x = v[6].x + v[7].x; p3.y = v[6].y + v[7].y; p3.z = v[6].z + v[7].z; p3.w = v[6].w + v[7].w;
        p0.x += p1.x; p0.y += p1.y; p0.z += p1.z; p0.w += p1.w;
        p2.x += p3.x; p2.y += p3.y; p2.z += p3.z; p2.w += p3.w;
        acc.x += p0.x + p2.x; acc.y += p0.y + p2.y;
        acc.z += p0.z + p2.z; acc.w += p0.w + p2.w;
    }
    for (; j < e; ++j) {
        int c = g_dst[j];
        float4 v = *(const float4*)(g_WAT + (size_t)c * HF + lane * 4);
        acc.x += v.x; acc.y += v.y; acc.z += v.z; acc.w += v.w;
    }
    acc.x = rna(acc.x); acc.y = rna(acc.y); acc.z = rna(acc.z); acc.w = rna(acc.w);
    *((float4*)(g_cat + (size_t)w * (2 * HF) + lane * 4)) = acc;
}

// ---------------- tf32 mma.sync GEMM (2-stage) -------------------------------
// RNDA: rna-round A fragments (raw fp32 A). RNDS: rna-round stores.
// B must be pre-rounded. EPI 0: plain, 2: relu. GUARD: zfill rows>=NN.
template<int BN, int EPI, int GUARD, int RNDA, int RNDS>
__global__ __launch_bounds__(256)
void k_mm(const float* __restrict__ A, int lda,
          const float* __restrict__ B,
          const float* __restrict__ bias,
          float* __restrict__ C, int ldc, int K)
{
    constexpr int BM = 128, BK = 16, STR = 20;
    constexpr int WXn = 4, WTN = BN / WXn;
    constexpr int NF = WTN / 8;
    constexpr int MF = 4;
    __shared__ __align__(16) float As[2][BM * STR];
    __shared__ __align__(16) float Bs[2][BN * STR];

    const int tid  = threadIdx.x;
    const int lane = tid & 31, warp = tid >> 5;
    const int wy = warp / WXn, wx = warp % WXn;
    const int g = lane >> 2, tg = lane & 3;
    const int bm = blockIdx.x * BM;

    float acc[MF][NF][4];
    #pragma unroll
    for (int i = 0; i < MF; ++i)
        #pragma unroll
        for (int j = 0; j < NF; ++j)
            #pragma unroll
            for (int c = 0; c < 4; ++c) acc[i][j][c] = 0.f;

    const uint32_t aS = s2u(As), bS = s2u(Bs);
    const int T = K / BK;

    auto load_tiles = [&](int t, int st) {
        const int k0 = t * BK;
        #pragma unroll
        for (int i = 0; i < BM * 4 / 256; ++i) {
            int idx = tid + i * 256;
            int r = idx >> 2, ch = idx & 3;
            uint32_t d = aS + (uint32_t)(st * BM * STR + r * STR + ch * 4) * 4;
            if (GUARD) {
                bool v = (bm + r) < NN;
                cp16z(d, A + (v ? ((size_t)(bm + r) * lda + k0 + ch * 4) : 0), v ? 16 : 0);
            } else {
                cp16(d, A + (size_t)(bm + r) * lda + k0 + ch * 4);
            }
        }
        #pragma unroll
        for (int i = 0; i < BN * 4 / 256; ++i) {
            int idx = tid + i * 256;
            int r = idx >> 2, ch = idx & 3;
            cp16(bS + (uint32_t)(st * BN * STR + r * STR + ch * 4) * 4,
                 B + (size_t)r * K + k0 + ch * 4);
        }
        asm volatile("cp.async.commit_group;");
    };

    load_tiles(0, 0);

    for (int t = 0; t < T; ++t) {
        const int cur = t & 1;
        if (t + 1 < T) {
            load_tiles(t + 1, cur ^ 1);
            asm volatile("cp.async.wait_group 1;");
        } else {
            asm volatile("cp.async.wait_group 0;");
        }
        __syncthreads();

        const float* as = As[cur];
        const float* bs = Bs[cur];
        #pragma unroll
        for (int ks = 0; ks < 2; ++ks) {
            uint32_t af[MF][4], bf[NF][2];
            #pragma unroll
            for (int mf = 0; mf < MF; ++mf) {
                int r0 = (wy * 64 + mf * 16 + g) * STR + ks * 8 + tg;
                if (RNDA) {
                    af[mf][0] = rnau(as[r0]);
                    af[mf][1] = rnau(as[r0 + 8 * STR]);
                    af[mf][2] = rnau(as[r0 + 4]);
                    af[mf][3] = rnau(as[r0 + 8 * STR + 4]);
                } else {
                    af[mf][0] = __float_as_uint(as[r0]);
                    af[mf][1] = __float_as_uint(as[r0 + 8 * STR]);
                    af[mf][2] = __float_as_uint(as[r0 + 4]);
                    af[mf][3] = __float_as_uint(as[r0 + 8 * STR + 4]);
                }
            }
            #pragma unroll
            for (int nf = 0; nf < NF; ++nf) {
                int rb = (wx * WTN + nf * 8 + g) * STR + ks * 8 + tg;
                bf[nf][0] = __float_as_uint(bs[rb]);
                bf[nf][1] = __float_as_uint(bs[rb + 4]);
            }
            #pragma unroll
            for (int mf = 0; mf < MF; ++mf)
                #pragma unroll
                for (int nf = 0; nf < NF; ++nf)
                    MMA_TF32(acc[mf][nf], af[mf], bf[nf]);
        }
        __syncthreads();
    }

    #pragma unroll
    for (int nf = 0; nf < NF; ++nf) {
        int n0 = wx * WTN + nf * 8 + tg * 2;
        float b0 = bias[n0], b1 = bias[n0 + 1];
        #pragma unroll
        for (int mf = 0; mf < MF; ++mf) {
            #pragma unroll
            for (int half = 0; half < 2; ++half) {
                int m = bm + wy * 64 + mf * 16 + g + half * 8;
                if (m >= NN) continue;
                float v0 = acc[mf][nf][half * 2 + 0] + b0;
                float v1 = acc[mf][nf][half * 2 + 1] + b1;
                if (EPI == 2) { v0 = fmaxf(v0, 0.f); v1 = fmaxf(v1, 0.f); }
                if (RNDS) { v0 = rna(v0); v1 = rna(v1); }
                *(float2*)(C + (size_t)m * ldc + n0) = make_float2(v0, v1);
            }
        }
    }
}

// ---------------- fused GEMM2+GEMM3 (dynamic smem, zero-CVT mainloops) -------
#define MM23_AS     0
#define MM23_BS     (2 * 128 * 20)
#define MM23_H1     (4 * 128 * 20)
#define MM23_FLOATS (MM23_H1 + 128 * 132)
#define MM23_BYTES  (MM23_FLOATS * 4)

__global__ __launch_bounds__(256)
void k_mm23(const float* __restrict__ bW, const float* __restrict__ bf1)
{
    constexpr int BM = 128, BK = 16, STR = 20, STR2 = 132;
    constexpr int WXn = 4, WTN = 32, NF = 4, MF = 4;
    extern __shared__ float dyn[];
    float* As  = dyn + MM23_AS;
    float* Bs  = dyn + MM23_BS;
    float* h1s = dyn + MM23_H1;
    __shared__ float s_sum[HF], s_sq[HF];

    const int tid  = threadIdx.x;
    const int lane = tid & 31, warp = tid >> 5;
    const int wy = warp / WXn, wx = warp % WXn;
    const int g = lane >> 2, tg = lane & 3;
    const int bm = blockIdx.x * BM;
    const float* cat = g_cat;
    const float* W   = g_Wr;
    const float* Wf1 = g_Wf1r;

    if (tid < HF) { s_sum[tid] = 0.f; s_sq[tid] = 0.f; }

    float acc[MF][NF][4];
    #pragma unroll
    for (int i = 0; i < MF; ++i)
        #pragma unroll
        for (int j = 0; j < NF; ++j)
            #pragma unroll
            for (int c = 0; c < 4; ++c) acc[i][j][c] = 0.f;

    const uint32_t aS = s2u(As), bS = s2u(Bs);

    auto loadB = [&](int t, int st) {
        const int k0 = t * BK;
        #pragma unroll
        for (int i = 0; i < 2; ++i) {
            int idx = tid + i * 256;
            int r = idx >> 2, ch = idx & 3;
            cp16(aS + (uint32_t)(st * BM * STR + r * STR + ch * 4) * 4,
                 cat + (size_t)(bm + r) * 256 + k0 + ch * 4);
        }
        #pragma unroll
        for (int i = 0; i < 2; ++i) {
            int idx = tid + i * 256;
            int r = idx >> 2, ch = idx & 3;
            cp16(bS + (uint32_t)(st * HF * STR + r * STR + ch * 4) * 4,
                 W + (size_t)r * 256 + k0 + ch * 4);
        }
        asm volatile("cp.async.commit_group;");
    };

    loadB(0, 0);
    for (int t = 0; t < 16; ++t) {
        const int cur = t & 1;
        if (t + 1 < 16) {
            loadB(t + 1, cur ^ 1);
            asm volatile("cp.async.wait_group 1;");
        } else {
            asm volatile("cp.async.wait_group 0;");
        }
        __syncthreads();
        const float* as = As + cur * BM * STR;
        const float* bs = Bs + cur * HF * STR;
        #pragma unroll
        for (int ks = 0; ks < 2; ++ks) {
            uint32_t af[MF][4], bf[NF][2];
            #pragma unroll
            for (int mf = 0; mf < MF; ++mf) {
                int r0 = (wy * 64 + mf * 16 + g) * STR + ks * 8 + tg;
                af[mf][0] = __float_as_uint(as[r0]);
                af[mf][1] = __float_as_uint(as[r0 + 8 * STR]);
                af[mf][2] = __float_as_uint(as[r0 + 4]);
                af[mf][3] = __float_as_uint(as[r0 + 8 * STR + 4]);
            }
            #pragma unroll
            for (int nf = 0; nf < NF; ++nf) {
                int rb = (wx * WTN + nf * 8 + g) * STR + ks * 8 + tg;
                bf[nf][0] = __float_as_uint(bs[rb]);
                bf[nf][1] = __float_as_uint(bs[rb + 4]);
            }
            #pragma unroll
            for (int mf = 0; mf < MF; ++mf)
                #pragma unroll
                for (int nf = 0; nf < NF; ++nf)
                    MMA_TF32(acc[mf][nf], af[mf], bf[nf]);
        }
        __syncthreads();
    }

    // prefetch stage-C B tile 0 (Wf1)
    {
        #pragma unroll
        for (int i = 0; i < 2; ++i) {
            int idx = tid + i * 256;
            int r = idx >> 2, ch = idx & 3;
            cp16(bS + (uint32_t)(r * STR + ch * 4) * 4,
                 Wf1 + (size_t)r * HF + ch * 4);
        }
        asm volatile("cp.async.commit_group;");
    }

    // stage-B epilogue: skip + relu + rna -> h1s
    #pragma unroll
    for (int nf = 0; nf < NF; ++nf) {
        int n0 = wx * WTN + nf * 8 + tg * 2;
        float b0 = bW[n0], b1 = bW[n0 + 1];
        #pragma unroll
        for (int mf = 0; mf < MF; ++mf) {
            #pragma unroll
            for (int half = 0; half < 2; ++half) {
                int ml = wy * 64 + mf * 16 + g + half * 8;
                const float* sp = cat + (size_t)(bm + ml) * 256;
                float v0 = acc[mf][nf][half * 2 + 0] + b0 + sp[n0]     + sp[128 + n0];
                float v1 = acc[mf][nf][half * 2 + 1] + b1 + sp[n0 + 1] + sp[128 + n0 + 1];
                v0 = rna(fmaxf(v0, 0.f)); v1 = rna(fmaxf(v1, 0.f));
                *(float2*)(h1s + ml * STR2 + n0) = make_float2(v0, v1);
                acc[mf][nf][half * 2 + 0] = 0.f;
                acc[mf][nf][half * 2 + 1] = 0.f;
            }
        }
    }
    __syncthreads();

    // stage C: K = 128, A from h1s, B = Wf1
    auto loadC = [&](int t, int st) {
        const int k0 = t * BK;
        #pragma unroll
        for (int i = 0; i < 2; ++i) {
            int idx = tid + i * 256;
            int r = idx >> 2, ch = idx & 3;
            cp16(bS + (uint32_t)(st * HF * STR + r * STR + ch * 4) * 4,
                 Wf1 + (size_t)r * HF + k0 + ch * 4);
        }
        asm volatile("cp.async.commit_group;");
    };

    for (int t = 0; t < 8; ++t) {
        const int cur = t & 1;
        if (t + 1 < 8) {
            loadC(t + 1, cur ^ 1);
            asm volatile("cp.async.wait_group 1;");
        } else {
            asm volatile("cp.async.wait_group 0;");
        }
        __syncthreads();
        const float* bs = Bs + cur * HF * STR;
        const int kb = t * BK;
        #pragma unroll
        for (int ks = 0; ks < 2; ++ks) {
            uint32_t af[MF][4], bf[NF][2];
            #pragma unroll
            for (int mf = 0; mf < MF; ++mf) {
                int r0 = (wy * 64 + mf * 16 + g) * STR2 + kb + ks * 8 + tg;
                af[mf][0] = __float_as_uint(h1s[r0]);
                af[mf][1] = __float_as_uint(h1s[r0 + 8 * STR2]);
                af[mf][2] = __float_as_uint(h1s[r0 + 4]);
                af[mf][3] = __float_as_uint(h1s[r0 + 8 * STR2 + 4]);
            }
            #pragma unroll
            for (int nf = 0; nf < NF; ++nf) {
                int rb = (wx * WTN + nf * 8 + g) * STR + ks * 8 + tg;
                bf[nf][0] = __float_as_uint(bs[rb]);
                bf[nf][1] = __float_as_uint(bs[rb + 4]);
            }
            #pragma unroll
            for (int mf = 0; mf < MF; ++mf)
                #pragma unroll
                for (int nf = 0; nf < NF; ++nf)
                    MMA_TF32(acc[mf][nf], af[mf], bf[nf]);
        }
        __syncthreads();
    }

    // stage-C epilogue: relu; stats on unrounded; store rounded g_t
    #pragma unroll
    for (int nf = 0; nf < NF; ++nf) {
        int n0 = wx * WTN + nf * 8 + tg * 2;
        float b0 = bf1[n0], b1 = bf1[n0 + 1];
        float ps0 = 0.f, pq0 = 0.f, ps1 = 0.f, pq1 = 0.f;
        #pragma unroll
        for (int mf = 0; mf < MF; ++mf) {
            #pragma unroll
            for (int half = 0; half < 2; ++half) {
                int m = bm + wy * 64 + mf * 16 + g + half * 8;
                if (m >= NN) continue;
                float v0 = fmaxf(acc[mf][nf][half * 2 + 0] + b0, 0.f);
                float v1 = fmaxf(acc[mf][nf][half * 2 + 1] + b1, 0.f);
                ps0 += v0; pq0 += v0 * v0; ps1 += v1; pq1 += v1 * v1;
                *(float2*)(g_t + (size_t)m * HF + n0) = make_float2(rna(v0), rna(v1));
            }
        }
        #pragma unroll
        for (int msk = 16; msk >= 4; msk >>= 1) {
            ps0 += __shfl_xor_sync(0xffffffffu, ps0, msk);
            pq0 += __shfl_xor_sync(0xffffffffu, pq0, msk);
            ps1 += __shfl_xor_sync(0xffffffffu, ps1, msk);
            pq1 += __shfl_xor_sync(0xffffffffu, pq1, msk);
        }
        if (g == 0) {
            atomicAdd(&s_sum[n0],     ps0); atomicAdd(&s_sq[n0],     pq0);
            atomicAdd(&s_sum[n0 + 1], ps1); atomicAdd(&s_sq[n0 + 1], pq1);
        }
    }
    __syncthreads();
    if (tid < HF) {
        atomicAdd(&g_sum[tid],   s_sum[tid]);
        atomicAdd(&g_sumsq[tid], s_sq[tid]);
    }
}

// ---------------- fold BN affine into Wf2/bf2 (rounded) ----------------------
__global__ void k_fold(const float* __restrict__ gamma, const float* __restrict__ beta,
                       const float* __restrict__ Wf2,   const float* __restrict__ bf2,
                       int M) {
    __shared__ float a[HF], b[HF];
    int t = threadIdx.x;
    if (t < HF) {
        float inv  = 1.f / (float)M;
        float mean = g_sum[t] * inv;
        float var  = g_sumsq[t] * inv - mean * mean;
        float av   = gamma[t] * rsqrtf(var + 1e-5f);
        a[t] = av;
        b[t] = beta[t] - mean * av;
    }
    __syncthreads();
    for (int i = t; i < OF * HF; i += blockDim.x)
        g_Wf2p[i] = rna(Wf2[i] * a[i & (HF - 1)]);
    if (t < OF) {
        float s = bf2[t];
        for (int h = 0; h < HF; ++h) s += b[h] * Wf2[t * HF + h];
        g_bf2p[t] = s;
    }
}

// -----------------------------------------------------------------------------
extern "C" void kernel_launch(void* const* d_in, const int* in_sizes, int n_in,
                              void* d_out, int out_size) {
    const float* x     = (const float*)d_in[0];
    const int*   ei    = (const int*)  d_in[1];
    const float* WA    = (const float*)d_in[2];
    const float* bA    = (const float*)d_in[3];
    const float* WX    = (const float*)d_in[4];
    const float* bX    = (const float*)d_in[5];
    const float* W     = (const float*)d_in[6];
    const float* bW    = (const float*)d_in[7];
    const float* Wf1   = (const float*)d_in[8];
    const float* bf1   = (const float*)d_in[9];
    const float* gamma = (const float*)d_in[10];
    const float* beta  = (const float*)d_in[11];
    const float* Wf2   = (const float*)d_in[12];
    const float* bf2   = (const float*)d_in[13];
    float* out = (float*)d_out;

    const int E = in_sizes[1] / 2;
    const int M = NN;
    const int* row = ei;
    const int* col = ei + E;

    float *pCat, *pT, *pWXr, *pW2, *pB2;
    cudaGetSymbolAddress((void**)&pCat, g_cat);
    cudaGetSymbolAddress((void**)&pT,   g_t);
    cudaGetSymbolAddress((void**)&pWXr, g_WXr);
    cudaGetSymbolAddress((void**)&pW2,  g_Wf2p);
    cudaGetSymbolAddress((void**)&pB2,  g_bf2p);

    static int inited = 0;
    static cudaStream_t sT, sG;
    static cudaEvent_t evRoot, evT, evG;
    if (!inited) {
        cudaFuncSetAttribute(k_mm23, cudaFuncAttributeMaxDynamicSharedMemorySize,
                             MM23_BYTES);
        cudaStreamCreateWithFlags(&sT, cudaStreamNonBlocking);
        cudaStreamCreateWithFlags(&sG, cudaStreamNonBlocking);
        cudaEventCreateWithFlags(&evRoot, cudaEventDisableTiming);
        cudaEventCreateWithFlags(&evT,    cudaEventDisableTiming);
        cudaEventCreateWithFlags(&evG,    cudaEventDisableTiming);
        inited = 1;
    }

    // ---- fork -----------------------------------------------------------------
    cudaEventRecord(evRoot, 0);
    cudaStreamWaitEvent(sT, evRoot, 0);
    cudaStreamWaitEvent(sG, evRoot, 0);

    // stream sT: transpose WA
    k_transpose<<<dim3((NN + 31) / 32, HF / 32), dim3(32, 8), 0, sT>>>(WA);
    cudaEventRecord(evT, sT);

    // stream sG: round weights, then GEMM1 (xX -> cat[:, 128:], rounded stores)
    k_roundw<<<(HF * INF + 255) / 256, 256, 0, sG>>>(WX, W, Wf1);
    k_mm<128, 0, 1, 1, 1><<<GBLK, 256, 0, sG>>>(x, INF, pWXr, bX, pCat + HF, 2 * HF, INF);
    cudaEventRecord(evG, sG);

    // stream 0: edge pipeline
    k_init<<<(NN + 255) / 256, 256>>>();
    k_hist<<<(E / 8 + 255) / 256, 256>>>(row, E);
    k_scanA<<<SCB, 256>>>();
    k_scanB<<<1, 256>>>();
    k_scanC<<<SCB, 256>>>(E);
    k_bin<<<(E / 8 + 255) / 256, 256>>>(row, col, E);

    // join transpose, then gather
    cudaStreamWaitEvent(0, evT, 0);
    k_gather<<<(NN * 32 + 255) / 256, 256>>>(bA);

    // join GEMM1 (+roundw), then fused GEMM2+3 (zero-CVT mainloops)
    cudaStreamWaitEvent(0, evG, 0);
    k_mm23<<<GBLK, 256, MM23_BYTES>>>(bW, bf1);

    // fold BN (rounded Wf2'), final GEMM (zero-CVT)
    k_fold<<<1, 256>>>(gamma, beta, Wf2, bf2, M);
    k_mm<64, 0, 0, 0, 0><<<GBLK, 256>>>(pT, HF, pW2, pB2, out, OF, HF);
}